// round 7
// baseline (speedup 1.0000x reference)
#include <cuda_runtime.h>
#include <cuda_fp16.h>
#include <cstdint>

typedef unsigned int u32;

#define NN 64
#define CC 128
#define TT 256
#define VV 25
#define OO 128
#define TILES 52
#define THREADS 512
#define SCALE 0.08838834764831845f   // 1/sqrt(128)

#define HS 136                        // half-row stride (pad 8): conflict-free
#define REGB 34816                    // bytes per [128][HS] fp16 region
// smem regions (bytes)
#define R0 0                          // x tile  -> Q' overlay
#define R1 34816                      // Wq      -> ps overlay [128][26] f32
#define R2 69632                      // Wk      -> outs overlay [128][129] f32
#define R3 104448                     // Wv      -> outs tail
#define R4 139264                     // K' (virgin)
#define R5 174080                     // V'^T (virgin)
#define BT_OFF 208896                 // bias table [25][25] f32
#define BQ_OFF 211400
#define BK_OFF 211912
#define BV_OFF 212424
#define SMEM_BYTES 212992

static __device__ __forceinline__ void mma16816(
    float* d, u32 a0, u32 a1, u32 a2, u32 a3, u32 b0, u32 b1)
{
    asm volatile(
        "mma.sync.aligned.m16n8k16.row.col.f32.f16.f16.f32 "
        "{%0,%1,%2,%3}, {%4,%5,%6,%7}, {%8,%9}, {%0,%1,%2,%3};"
        : "+f"(d[0]), "+f"(d[1]), "+f"(d[2]), "+f"(d[3])
        : "r"(a0), "r"(a1), "r"(a2), "r"(a3), "r"(b0), "r"(b1));
}
static __device__ __forceinline__ void ldmx4(u32* r, const __half* p) {
    u32 a = (u32)__cvta_generic_to_shared(p);
    asm volatile("ldmatrix.sync.aligned.m8n8.x4.shared.b16 {%0,%1,%2,%3}, [%4];"
        : "=r"(r[0]), "=r"(r[1]), "=r"(r[2]), "=r"(r[3]) : "r"(a));
}
static __device__ __forceinline__ u32 h2u(__half2 h) {
    u32 r; asm("mov.b32 %0, %1;" : "=r"(r) : "r"(*(u32*)&h)); return r;
}

__global__ void __launch_bounds__(THREADS, 1) phys_attn_mma(
    const float* __restrict__ x,
    const float* __restrict__ wq, const float* __restrict__ bq,
    const float* __restrict__ wk, const float* __restrict__ bk,
    const float* __restrict__ wv, const float* __restrict__ bv,
    const float* __restrict__ bias_emb,
    const int*   __restrict__ hop,
    float* __restrict__ out)
{
    extern __shared__ char sm[];
    __half* xhs = (__half*)(sm + R0);   // x, later Q'
    __half* wqs = (__half*)(sm + R1);
    __half* wks = (__half*)(sm + R2);
    __half* wvs = (__half*)(sm + R3);
    __half* kps = (__half*)(sm + R4);   // K'
    __half* vps = (__half*)(sm + R5);   // V'^T
    __half* qps = (__half*)(sm + R0);   // Q' overlay
    float* bias_s = (float*)(sm + BT_OFF);
    float* bqs = (float*)(sm + BQ_OFF);
    float* bks = (float*)(sm + BK_OFF);
    float* bvs = (float*)(sm + BV_OFF);
    float* ps   = (float*)(sm + R1);    // [128][26]
    float* outs = (float*)(sm + R2);    // [128][129]

    const int tid = threadIdx.x;
    const int wid = tid >> 5, lid = tid & 31;
    const int gr = lid >> 2, q4 = lid & 3;
    const int ms = wid >> 1;
    const int half = wid & 1;
    const int m0 = ms * 16;
    const int co = half * 64;

    // ldmatrix per-thread row/col selectors
    const int arow = (lid & 7) + ((lid >> 3) & 1) * 8;   // A pattern
    const int acol = ((lid >> 4) & 1) * 8;
    const int brow = (lid & 7) + ((lid >> 4) & 1) * 8;   // B pair pattern
    const int bcol = ((lid >> 3) & 1) * 8;

    const int n = blockIdx.x / TILES;
    const int tile = blockIdx.x - n * TILES;
    const int t0 = tile * 5;
    const int nvalid = (tile < 51) ? 125 : 25;

    // ---- stage weights fp32 -> fp16 ----
    for (int i = tid; i < 4096; i += THREADS) {
        int o = i >> 5, c4 = (i & 31) << 2;
        float4 fq = __ldg((const float4*)(wq + o * CC + c4));
        float4 fk = __ldg((const float4*)(wk + o * CC + c4));
        float4 fv = __ldg((const float4*)(wv + o * CC + c4));
        *(__half2*)(wqs + o * HS + c4)     = __floats2half2_rn(fq.x, fq.y);
        *(__half2*)(wqs + o * HS + c4 + 2) = __floats2half2_rn(fq.z, fq.w);
        *(__half2*)(wks + o * HS + c4)     = __floats2half2_rn(fk.x, fk.y);
        *(__half2*)(wks + o * HS + c4 + 2) = __floats2half2_rn(fk.z, fk.w);
        *(__half2*)(wvs + o * HS + c4)     = __floats2half2_rn(fv.x, fv.y);
        *(__half2*)(wvs + o * HS + c4 + 2) = __floats2half2_rn(fv.z, fv.w);
    }
    // ---- stage x tile fp16, zero-pad rows >= nvalid ----
    const float* xb = x + (size_t)n * CC * TT * VV + (size_t)t0 * VV;
    for (int i = tid; i < CC * 128; i += THREADS) {
        int c = i >> 7, m = i & 127;
        float val = (m < nvalid) ? __ldg(xb + (size_t)c * (TT * VV) + m) : 0.f;
        xhs[m * HS + c] = __float2half_rn(val);
    }
    if (tid < OO) {
        bqs[tid] = __ldg(bq + tid);
        bks[tid] = __ldg(bk + tid);
        bvs[tid] = __ldg(bv + tid);
    }
    for (int i = tid; i < VV * VV; i += THREADS)
        bias_s[i] = __ldg(bias_emb + __ldg(hop + i));
    __syncthreads();                       // #1

    // ---- cache A-fragments of x via ldmatrix ----
    u32 af[8][4];
#pragma unroll
    for (int kt = 0; kt < 8; ++kt)
        ldmx4(af[kt], xhs + (m0 + arow) * HS + kt * 16 + acol);
    __syncthreads();                       // #2 (x region may be overwritten later)

    float d[8][4];
    u32 b[4];

    // ================= K projection -> K' (R4, virgin; no barrier) ===========
#pragma unroll
    for (int j = 0; j < 8; ++j) { d[j][0] = d[j][1] = d[j][2] = d[j][3] = 0.f; }
#pragma unroll
    for (int kt = 0; kt < 8; ++kt) {
#pragma unroll
        for (int jp = 0; jp < 4; ++jp) {
            ldmx4(b, wks + (co + jp * 16 + brow) * HS + kt * 16 + bcol);
            mma16816(d[2 * jp],     af[kt][0], af[kt][1], af[kt][2], af[kt][3], b[0], b[1]);
            mma16816(d[2 * jp + 1], af[kt][0], af[kt][1], af[kt][2], af[kt][3], b[2], b[3]);
        }
    }
#pragma unroll
    for (int j = 0; j < 8; ++j) {
        int col = co + j * 8 + q4 * 2;
        float b0 = bks[col], b1 = bks[col + 1];
        *(__half2*)(kps + (m0 + gr) * HS + col) =
            __floats2half2_rn(d[j][0] + b0, d[j][1] + b1);
        *(__half2*)(kps + (m0 + gr + 8) * HS + col) =
            __floats2half2_rn(d[j][2] + b0, d[j][3] + b1);
    }

    // ================= V projection -> V'^T (R5, virgin; no barrier) =========
#pragma unroll
    for (int j = 0; j < 8; ++j) { d[j][0] = d[j][1] = d[j][2] = d[j][3] = 0.f; }
#pragma unroll
    for (int kt = 0; kt < 8; ++kt) {
#pragma unroll
        for (int jp = 0; jp < 4; ++jp) {
            ldmx4(b, wvs + (co + jp * 16 + brow) * HS + kt * 16 + bcol);
            mma16816(d[2 * jp],     af[kt][0], af[kt][1], af[kt][2], af[kt][3], b[0], b[1]);
            mma16816(d[2 * jp + 1], af[kt][0], af[kt][1], af[kt][2], af[kt][3], b[2], b[3]);
        }
    }
#pragma unroll
    for (int j = 0; j < 8; ++j) {
        int col = co + j * 8 + q4 * 2;
        float b0 = bvs[col], b1 = bvs[col + 1];
        vps[col * HS + (m0 + gr)]           = __float2half_rn(d[j][0] + b0);
        vps[(col + 1) * HS + (m0 + gr)]     = __float2half_rn(d[j][1] + b1);
        vps[col * HS + (m0 + gr + 8)]       = __float2half_rn(d[j][2] + b0);
        vps[(col + 1) * HS + (m0 + gr + 8)] = __float2half_rn(d[j][3] + b1);
    }

    // ================= Q projection -> Q' (R0 overlay; own rows) =============
#pragma unroll
    for (int j = 0; j < 8; ++j) { d[j][0] = d[j][1] = d[j][2] = d[j][3] = 0.f; }
#pragma unroll
    for (int kt = 0; kt < 8; ++kt) {
#pragma unroll
        for (int jp = 0; jp < 4; ++jp) {
            ldmx4(b, wqs + (co + jp * 16 + brow) * HS + kt * 16 + bcol);
            mma16816(d[2 * jp],     af[kt][0], af[kt][1], af[kt][2], af[kt][3], b[0], b[1]);
            mma16816(d[2 * jp + 1], af[kt][0], af[kt][1], af[kt][2], af[kt][3], b[2], b[3]);
        }
    }
#pragma unroll
    for (int j = 0; j < 8; ++j) {
        int col = co + j * 8 + q4 * 2;
        float b0 = bqs[col], b1 = bqs[col + 1];
        *(__half2*)(qps + (m0 + gr) * HS + col) =
            __floats2half2_rn(d[j][0] + b0, d[j][1] + b1);
        *(__half2*)(qps + (m0 + gr + 8) * HS + col) =
            __floats2half2_rn(d[j][2] + b0, d[j][3] + b1);
    }
    __syncthreads();                       // #3: Q', K', V'^T ready everywhere

    // ---- per-warp block-diagonal window ----
    const int rlo = m0;
    const int rhi = min(m0 + 16, nvalid);
    const bool wact = rlo < nvalid;
    int wlo = 0, whi = 0;
    if (wact) {
        wlo = (rlo / VV) * VV;
        whi = min(((rhi - 1) / VV) * VV + VV, nvalid);
    }

    // ================= S = Q' K'^T (windowed n-tiles) =================
#pragma unroll
    for (int j = 0; j < 8; ++j) { d[j][0] = d[j][1] = d[j][2] = d[j][3] = 0.f; }
    if (wact) {
        int jlo = max(0, (wlo - co) >> 3);
        int jhi = min(8, (whi - co + 7) >> 3);
        if (jlo < jhi) {
#pragma unroll
            for (int kt = 0; kt < 8; ++kt) {
                u32 a[4];
                ldmx4(a, qps + (m0 + arow) * HS + kt * 16 + acol);
                int base = kt * 16 + q4 * 2;
                for (int j = jlo; j < jhi; ++j) {
                    const __half* bp = kps + (co + j * 8 + gr) * HS + base;
                    mma16816(d[j], a[0], a[1], a[2], a[3],
                             *(const u32*)bp, *(const u32*)(bp + 8));
                }
            }
        }
    }

    // ---- scatter S (scaled + bias) into compact ps[m][26] ----
    const int mA = m0 + gr, mB = mA + 8;
    const bool actA = mA < nvalid, actB = mB < nvalid;
    const int tbA = mA / VV, vlA = mA - tbA * VV, loA = tbA * VV;
    const int tbB = mB / VV, vlB = mB - tbB * VV, loB = tbB * VV;
    if (wact) {
#pragma unroll
        for (int j = 0; j < 8; ++j) {
            int w = co + j * 8 + q4 * 2;
            int rA = w - loA, rB = w - loB;
            if (actA && rA >= 0 && rA < VV)
                ps[mA * 26 + rA] = fmaf(d[j][0], SCALE, bias_s[vlA * VV + rA]);
            if (actA && rA + 1 >= 0 && rA + 1 < VV)
                ps[mA * 26 + rA + 1] = fmaf(d[j][1], SCALE, bias_s[vlA * VV + rA + 1]);
            if (actB && rB >= 0 && rB < VV)
                ps[mB * 26 + rB] = fmaf(d[j][2], SCALE, bias_s[vlB * VV + rB]);
            if (actB && rB + 1 >= 0 && rB + 1 < VV)
                ps[mB * 26 + rB + 1] = fmaf(d[j][3], SCALE, bias_s[vlB * VV + rB + 1]);
        }
    }
    __syncthreads();                       // #4

    // ================= softmax (thread per row) =================
    if (tid < 128 && tid < nvalid) {
        float* row = ps + tid * 26;
        float mx = row[0];
#pragma unroll
        for (int w = 1; w < VV; ++w) mx = fmaxf(mx, row[w]);
        float sum = 0.f;
        float e[VV];
#pragma unroll
        for (int w = 0; w < VV; ++w) { e[w] = __expf(row[w] - mx); sum += e[w]; }
        float inv = 1.f / sum;
#pragma unroll
        for (int w = 0; w < VV; ++w) row[w] = e[w] * inv;
    }
    __syncthreads();                       // #5

    // ================= AV = P V' (windowed k-steps) =================
#pragma unroll
    for (int j = 0; j < 8; ++j) { d[j][0] = d[j][1] = d[j][2] = d[j][3] = 0.f; }
    if (wact) {
        int ktlo = wlo >> 4;
        int kthi = (whi + 15) >> 4;
        for (int kt = ktlo; kt < kthi; ++kt) {
            int k0 = kt * 16 + q4 * 2;
            int rA0 = k0 - loA, rB0 = k0 - loB;
            float pA0 = (actA && rA0 >= 0 && rA0 < VV) ? ps[mA * 26 + rA0] : 0.f;
            float pA1 = (actA && rA0 + 1 >= 0 && rA0 + 1 < VV) ? ps[mA * 26 + rA0 + 1] : 0.f;
            float pB0 = (actB && rB0 >= 0 && rB0 < VV) ? ps[mB * 26 + rB0] : 0.f;
            float pB1 = (actB && rB0 + 1 >= 0 && rB0 + 1 < VV) ? ps[mB * 26 + rB0 + 1] : 0.f;
            int rA8 = rA0 + 8, rB8 = rB0 + 8;
            float pA8 = (actA && rA8 >= 0 && rA8 < VV) ? ps[mA * 26 + rA8] : 0.f;
            float pA9 = (actA && rA8 + 1 >= 0 && rA8 + 1 < VV) ? ps[mA * 26 + rA8 + 1] : 0.f;
            float pB8 = (actB && rB8 >= 0 && rB8 < VV) ? ps[mB * 26 + rB8] : 0.f;
            float pB9 = (actB && rB8 + 1 >= 0 && rB8 + 1 < VV) ? ps[mB * 26 + rB8 + 1] : 0.f;
            u32 a0 = h2u(__floats2half2_rn(pA0, pA1));
            u32 a1 = h2u(__floats2half2_rn(pB0, pB1));
            u32 a2 = h2u(__floats2half2_rn(pA8, pA9));
            u32 a3 = h2u(__floats2half2_rn(pB8, pB9));
#pragma unroll
            for (int jp = 0; jp < 4; ++jp) {
                ldmx4(b, vps + (co + jp * 16 + brow) * HS + kt * 16 + bcol);
                mma16816(d[2 * jp],     a0, a1, a2, a3, b[0], b[1]);
                mma16816(d[2 * jp + 1], a0, a1, a2, a3, b[2], b[3]);
            }
        }
    }

    // ---- write outs[m][o] (R2/R3 overlay; Wk/Wv dead since #3) ----
#pragma unroll
    for (int j = 0; j < 8; ++j) {
        int col = co + j * 8 + q4 * 2;
        outs[mA * 129 + col]     = d[j][0];
        outs[mA * 129 + col + 1] = d[j][1];
        outs[mB * 129 + col]     = d[j][2];
        outs[mB * 129 + col + 1] = d[j][3];
    }
    __syncthreads();                       // #6

    // ---- coalesced store: warp per o-row ----
    float* ob = out + (size_t)n * OO * TT * VV + (size_t)t0 * VV;
    for (int orow = wid; orow < OO; orow += 16) {
        float* dst = ob + (size_t)orow * (TT * VV);
#pragma unroll
        for (int p = 0; p < 4; ++p) {
            int m = lid + p * 32;
            if (m < nvalid) dst[m] = outs[m * 129 + orow];
        }
    }
}

extern "C" void kernel_launch(void* const* d_in, const int* in_sizes, int n_in,
                              void* d_out, int out_size)
{
    const float* x   = (const float*)d_in[0];
    const float* wq  = (const float*)d_in[1];
    const float* bq  = (const float*)d_in[2];
    const float* wk  = (const float*)d_in[3];
    const float* bk  = (const float*)d_in[4];
    const float* wv  = (const float*)d_in[5];
    const float* bv  = (const float*)d_in[6];
    const float* be  = (const float*)d_in[7];
    const int*   hop = (const int*)d_in[8];
    float* out = (float*)d_out;

    cudaFuncSetAttribute(phys_attn_mma,
                         cudaFuncAttributeMaxDynamicSharedMemorySize, SMEM_BYTES);

    phys_attn_mma<<<NN * TILES, THREADS, SMEM_BYTES>>>(
        x, wq, bq, wk, bk, wv, bv, be, hop, out);
}

// round 8
// speedup vs baseline: 1.0894x; 1.0894x over previous
#include <cuda_runtime.h>
#include <cuda_fp16.h>
#include <cstdint>

typedef unsigned int u32;

#define NN 64
#define CC 128
#define TT 256
#define VV 25
#define OO 128
#define TILES 52
#define NITEMS (NN * TILES)     // 3328
#define THREADS 512
#define SCALE 0.08838834764831845f   // 1/sqrt(128)

// swizzled fp16 tile: [128 rows][128 halves], row stride 256B, 16B-chunk XOR swizzle
#define WKS_OFF 0
#define WVS_OFF 32768
#define WQB_OFF 65536          // Wq image / Q' overlay
#define XS_OFF  98304          // x tile (streamed)
#define KPS_OFF 131072         // K' ; outs overlay base
#define VPS_OFF 163840         // V'^T
#define PS_OFF  196608         // scores/attn [128][26] f32
#define BT_OFF  209920         // bias table [25][25] f32
#define BQ_OFF  212420
#define BK_OFF  212932
#define BV_OFF  213444
#define SMEM_BYTES 214016

__device__ __half g_wh[3][OO * CC];   // packed fp16 weights [o][c]

__global__ void __launch_bounds__(256) prep_w(
    const float* __restrict__ wq, const float* __restrict__ wk,
    const float* __restrict__ wv)
{
    int i = blockIdx.x * blockDim.x + threadIdx.x;
    if (i < OO * CC) {
        g_wh[0][i] = __float2half_rn(wq[i]);
        g_wh[1][i] = __float2half_rn(wk[i]);
        g_wh[2][i] = __float2half_rn(wv[i]);
    }
}

// byte offset of half (row, colh) in swizzled tile
static __device__ __forceinline__ int swz(int row, int colh) {
    return (row << 8) + ((((colh >> 3) ^ (row & 7))) << 4) + ((colh & 7) << 1);
}

static __device__ __forceinline__ void mma16816(
    float* d, u32 a0, u32 a1, u32 a2, u32 a3, u32 b0, u32 b1)
{
    asm volatile(
        "mma.sync.aligned.m16n8k16.row.col.f32.f16.f16.f32 "
        "{%0,%1,%2,%3}, {%4,%5,%6,%7}, {%8,%9}, {%0,%1,%2,%3};"
        : "+f"(d[0]), "+f"(d[1]), "+f"(d[2]), "+f"(d[3])
        : "r"(a0), "r"(a1), "r"(a2), "r"(a3), "r"(b0), "r"(b1));
}
static __device__ __forceinline__ void ldmx4(u32* r, const void* p) {
    u32 a = (u32)__cvta_generic_to_shared(p);
    asm volatile("ldmatrix.sync.aligned.m8n8.x4.shared.b16 {%0,%1,%2,%3}, [%4];"
        : "=r"(r[0]), "=r"(r[1]), "=r"(r[2]), "=r"(r[3]) : "r"(a));
}
static __device__ __forceinline__ u32 h2u(__half2 h) {
    u32 r; asm("mov.b32 %0, %1;" : "=r"(r) : "r"(*(u32*)&h)); return r;
}

__global__ void __launch_bounds__(THREADS, 1) phys_attn_pers(
    const float* __restrict__ x,
    const float* __restrict__ bq, const float* __restrict__ bk,
    const float* __restrict__ bv,
    const float* __restrict__ bias_emb, const int* __restrict__ hop,
    float* __restrict__ out)
{
    extern __shared__ __align__(16) char sm[];
    char* wks = sm + WKS_OFF;
    char* wvs = sm + WVS_OFF;
    char* wqb = sm + WQB_OFF;
    char* xs  = sm + XS_OFF;
    char* kps = sm + KPS_OFF;
    char* vps = sm + VPS_OFF;
    float* ps     = (float*)(sm + PS_OFF);
    float* outs   = (float*)(sm + KPS_OFF);   // overlay after AV
    float* bias_s = (float*)(sm + BT_OFF);
    float* bqs    = (float*)(sm + BQ_OFF);
    float* bks    = (float*)(sm + BK_OFF);
    float* bvs    = (float*)(sm + BV_OFF);

    const int tid = threadIdx.x;
    const int wid = tid >> 5, lid = tid & 31;
    const int gr = lid >> 2, q4 = lid & 3;
    const int ms = wid >> 1, half = wid & 1;
    const int m0 = ms * 16;
    const int co = half * 64;

    const int arow = (lid & 7) + ((lid >> 3) & 1) * 8;
    const int acol = ((lid >> 4) & 1) * 8;
    const int brow = (lid & 7) + ((lid >> 4) & 1) * 8;
    const int bcol = ((lid >> 3) & 1) * 8;

    // ---- prologue: weights (once), biases, bias table ----
    uint4 wqr[4];
#pragma unroll
    for (int k = 0; k < 4; ++k) {
        int h0 = tid * 32 + k * 8;
        int o = h0 >> 7, c = h0 & 127;
        int off = swz(o, c);
        *(uint4*)(wks + off) = *(const uint4*)(&g_wh[1][h0]);
        *(uint4*)(wvs + off) = *(const uint4*)(&g_wh[2][h0]);
        wqr[k] = *(const uint4*)(&g_wh[0][h0]);
    }
    if (tid < OO) {
        bqs[tid] = __ldg(bq + tid);
        bks[tid] = __ldg(bk + tid);
        bvs[tid] = __ldg(bv + tid);
    }
    for (int i = tid; i < VV * VV; i += THREADS)
        bias_s[i] = __ldg(bias_emb + __ldg(hop + i));

    // ---- stage first item's x ----
    int it = blockIdx.x;
    if (it < NITEMS) {
        int n = it / TILES, tile = it - n * TILES;
        int nval = (tile < 51) ? 125 : 25;
        const float* xb = x + (size_t)n * (CC * TT * VV) + (size_t)(tile * 5) * VV;
#pragma unroll 4
        for (int p = 0; p < 32; ++p) {
            int i = tid + p * THREADS;
            int c = i >> 7, m = i & 127;
            float val = (m < nval) ? __ldg(xb + c * (TT * VV) + m) : 0.f;
            *(__half*)(xs + swz(m, c)) = __float2half_rn(val);
        }
    }
    __syncthreads();

    for (; it < NITEMS; it += gridDim.x) {
        const int n = it / TILES, tile = it - n * TILES;
        const int t0 = tile * 5;
        const int nvalid = (tile < 51) ? 125 : 25;
        const int nit = it + gridDim.x;
        const bool hn = nit < NITEMS;
        int nnval = 0;
        const float* nxb = x;
        if (hn) {
            int nn = nit / TILES, ntile = nit - nn * TILES;
            nnval = (ntile < 51) ? 125 : 25;
            nxb = x + (size_t)nn * (CC * TT * VV) + (size_t)(ntile * 5) * VV;
        }

        // P0: cache x A-fragments (x smem dead afterwards)
        u32 af[8][4];
#pragma unroll
        for (int kt = 0; kt < 8; ++kt)
            ldmx4(af[kt], xs + swz(m0 + arow, kt * 16 + acol));
        // P1: refill Wq image (region free: prev Q' dead after prev S)
#pragma unroll
        for (int k = 0; k < 4; ++k) {
            int h0 = tid * 32 + k * 8;
            *(uint4*)(wqb + swz(h0 >> 7, h0 & 127)) = wqr[k];
        }
        __syncthreads();                      // BAR1

        float d[8][4];
        u32 b[4];
        float xr[16];

        // P2a: next-x chunk1 LDG (overlapped with K-proj)
        if (hn) {
#pragma unroll
            for (int p = 0; p < 16; ++p) {
                int i = tid + p * THREADS;
                int c = i >> 7, m = i & 127;
                xr[p] = (m < nnval) ? __ldg(nxb + c * (TT * VV) + m) : 0.f;
            }
        }

        // ---------- K projection ----------
#pragma unroll
        for (int j = 0; j < 8; ++j) { d[j][0]=d[j][1]=d[j][2]=d[j][3]=0.f; }
#pragma unroll
        for (int kt = 0; kt < 8; ++kt) {
#pragma unroll
            for (int jp = 0; jp < 4; ++jp) {
                ldmx4(b, wks + swz(co + jp * 16 + brow, kt * 16 + bcol));
                mma16816(d[2*jp],   af[kt][0],af[kt][1],af[kt][2],af[kt][3], b[0],b[1]);
                mma16816(d[2*jp+1], af[kt][0],af[kt][1],af[kt][2],af[kt][3], b[2],b[3]);
            }
        }
#pragma unroll
        for (int j = 0; j < 8; ++j) {
            int col = co + j * 8 + q4 * 2;
            float b0 = bks[col], b1 = bks[col + 1];
            *(__half2*)(kps + swz(m0 + gr, col)) =
                __floats2half2_rn(d[j][0] + b0, d[j][1] + b1);
            *(__half2*)(kps + swz(m0 + gr + 8, col)) =
                __floats2half2_rn(d[j][2] + b0, d[j][3] + b1);
        }
        // P4a: chunk1 STS
        if (hn) {
#pragma unroll
            for (int p = 0; p < 16; ++p) {
                int i = tid + p * THREADS;
                *(__half*)(xs + swz(i & 127, i >> 7)) = __float2half_rn(xr[p]);
            }
        }
        // P2b: next-x chunk2 LDG
        if (hn) {
#pragma unroll
            for (int p = 0; p < 16; ++p) {
                int i = tid + (p + 16) * THREADS;
                int c = i >> 7, m = i & 127;
                xr[p] = (m < nnval) ? __ldg(nxb + c * (TT * VV) + m) : 0.f;
            }
        }

        // ---------- V projection ----------
#pragma unroll
        for (int j = 0; j < 8; ++j) { d[j][0]=d[j][1]=d[j][2]=d[j][3]=0.f; }
#pragma unroll
        for (int kt = 0; kt < 8; ++kt) {
#pragma unroll
            for (int jp = 0; jp < 4; ++jp) {
                ldmx4(b, wvs + swz(co + jp * 16 + brow, kt * 16 + bcol));
                mma16816(d[2*jp],   af[kt][0],af[kt][1],af[kt][2],af[kt][3], b[0],b[1]);
                mma16816(d[2*jp+1], af[kt][0],af[kt][1],af[kt][2],af[kt][3], b[2],b[3]);
            }
        }
#pragma unroll
        for (int j = 0; j < 8; ++j) {   // V'^T (+bv): rows = o, cols = m
            int col = co + j * 8 + q4 * 2;
            float b0 = bvs[col], b1 = bvs[col + 1];
            *(__half*)(vps + swz(col,     m0 + gr))     = __float2half_rn(d[j][0] + b0);
            *(__half*)(vps + swz(col + 1, m0 + gr))     = __float2half_rn(d[j][1] + b1);
            *(__half*)(vps + swz(col,     m0 + gr + 8)) = __float2half_rn(d[j][2] + b0);
            *(__half*)(vps + swz(col + 1, m0 + gr + 8)) = __float2half_rn(d[j][3] + b1);
        }
        // P4b: chunk2 STS
        if (hn) {
#pragma unroll
            for (int p = 0; p < 16; ++p) {
                int i = tid + (p + 16) * THREADS;
                *(__half*)(xs + swz(i & 127, i >> 7)) = __float2half_rn(xr[p]);
            }
        }

        // ---------- Q projection (reads wqb) ----------
#pragma unroll
        for (int j = 0; j < 8; ++j) { d[j][0]=d[j][1]=d[j][2]=d[j][3]=0.f; }
#pragma unroll
        for (int kt = 0; kt < 8; ++kt) {
#pragma unroll
            for (int jp = 0; jp < 4; ++jp) {
                ldmx4(b, wqb + swz(co + jp * 16 + brow, kt * 16 + bcol));
                mma16816(d[2*jp],   af[kt][0],af[kt][1],af[kt][2],af[kt][3], b[0],b[1]);
                mma16816(d[2*jp+1], af[kt][0],af[kt][1],af[kt][2],af[kt][3], b[2],b[3]);
            }
        }
        __syncthreads();                      // BAR2: wqb readers done; K',V',x visible
        // P7: Q' (+bq) into wqb
#pragma unroll
        for (int j = 0; j < 8; ++j) {
            int col = co + j * 8 + q4 * 2;
            float b0 = bqs[col], b1 = bqs[col + 1];
            *(__half2*)(wqb + swz(m0 + gr, col)) =
                __floats2half2_rn(d[j][0] + b0, d[j][1] + b1);
            *(__half2*)(wqb + swz(m0 + gr + 8, col)) =
                __floats2half2_rn(d[j][2] + b0, d[j][3] + b1);
        }
        __syncthreads();                      // BAR3: Q' visible

        // ---- per-warp block-diagonal window ----
        const int rhi = min(m0 + 16, nvalid);
        const bool wact = m0 < nvalid;
        int wlo = 0, whi = 0;
        if (wact) {
            wlo = (m0 / VV) * VV;
            whi = min(((rhi - 1) / VV) * VV + VV, nvalid);
        }

        // ---------- S = Q' K'^T (windowed) ----------
#pragma unroll
        for (int j = 0; j < 8; ++j) { d[j][0]=d[j][1]=d[j][2]=d[j][3]=0.f; }
        if (wact) {
            int jlo = max(0, (wlo - co) >> 3);
            int jhi = min(8, (whi - co + 7) >> 3);
            if (jlo < jhi) {
#pragma unroll
                for (int kt = 0; kt < 8; ++kt) {
                    u32 a[4];
                    ldmx4(a, wqb + swz(m0 + arow, kt * 16 + acol));
                    for (int j = jlo; j < jhi; ++j) {
                        int nrow = co + j * 8 + gr;
                        int base = nrow << 8;
                        u32 b0 = *(const u32*)(kps + base +
                                  (((2 * kt) ^ (nrow & 7)) << 4) + (q4 << 2));
                        u32 b1 = *(const u32*)(kps + base +
                                  (((2 * kt + 1) ^ (nrow & 7)) << 4) + (q4 << 2));
                        mma16816(d[j], a[0], a[1], a[2], a[3], b0, b1);
                    }
                }
            }
        }
        // scatter scaled+biased scores into ps[m][26]
        const int mA = m0 + gr, mB = mA + 8;
        const bool actA = mA < nvalid, actB = mB < nvalid;
        const int tbA = mA / VV, vlA = mA - tbA * VV, loA = tbA * VV;
        const int tbB = mB / VV, vlB = mB - tbB * VV, loB = tbB * VV;
        if (wact) {
#pragma unroll
            for (int j = 0; j < 8; ++j) {
                int w = co + j * 8 + q4 * 2;
                int rA = w - loA, rB = w - loB;
                if (actA && rA >= 0 && rA < VV)
                    ps[mA * 26 + rA] = fmaf(d[j][0], SCALE, bias_s[vlA * VV + rA]);
                if (actA && rA + 1 >= 0 && rA + 1 < VV)
                    ps[mA * 26 + rA + 1] = fmaf(d[j][1], SCALE, bias_s[vlA * VV + rA + 1]);
                if (actB && rB >= 0 && rB < VV)
                    ps[mB * 26 + rB] = fmaf(d[j][2], SCALE, bias_s[vlB * VV + rB]);
                if (actB && rB + 1 >= 0 && rB + 1 < VV)
                    ps[mB * 26 + rB + 1] = fmaf(d[j][3], SCALE, bias_s[vlB * VV + rB + 1]);
            }
        }
        __syncthreads();                      // BAR4

        // ---------- softmax ----------
        if (tid < 128 && tid < nvalid) {
            float* row = ps + tid * 26;
            float mx = row[0];
#pragma unroll
            for (int w = 1; w < VV; ++w) mx = fmaxf(mx, row[w]);
            float sum = 0.f;
            float e[VV];
#pragma unroll
            for (int w = 0; w < VV; ++w) { e[w] = __expf(row[w] - mx); sum += e[w]; }
            float inv = 1.f / sum;
#pragma unroll
            for (int w = 0; w < VV; ++w) row[w] = e[w] * inv;
        }
        __syncthreads();                      // BAR5

        // ---------- AV = P V' (windowed) ----------
#pragma unroll
        for (int j = 0; j < 8; ++j) { d[j][0]=d[j][1]=d[j][2]=d[j][3]=0.f; }
        if (wact) {
            int ktlo = wlo >> 4;
            int kthi = (whi + 15) >> 4;
            for (int kt = ktlo; kt < kthi; ++kt) {
                int k0 = kt * 16 + q4 * 2;
                int rA0 = k0 - loA, rB0 = k0 - loB;
                float pA0 = (actA && rA0 >= 0 && rA0 < VV) ? ps[mA * 26 + rA0] : 0.f;
                float pA1 = (actA && rA0 + 1 >= 0 && rA0 + 1 < VV) ? ps[mA * 26 + rA0 + 1] : 0.f;
                float pB0 = (actB && rB0 >= 0 && rB0 < VV) ? ps[mB * 26 + rB0] : 0.f;
                float pB1 = (actB && rB0 + 1 >= 0 && rB0 + 1 < VV) ? ps[mB * 26 + rB0 + 1] : 0.f;
                int rA8 = rA0 + 8, rB8 = rB0 + 8;
                float pA8 = (actA && rA8 >= 0 && rA8 < VV) ? ps[mA * 26 + rA8] : 0.f;
                float pA9 = (actA && rA8 + 1 >= 0 && rA8 + 1 < VV) ? ps[mA * 26 + rA8 + 1] : 0.f;
                float pB8 = (actB && rB8 >= 0 && rB8 < VV) ? ps[mB * 26 + rB8] : 0.f;
                float pB9 = (actB && rB8 + 1 >= 0 && rB8 + 1 < VV) ? ps[mB * 26 + rB8 + 1] : 0.f;
                u32 a0 = h2u(__floats2half2_rn(pA0, pA1));
                u32 a1 = h2u(__floats2half2_rn(pB0, pB1));
                u32 a2 = h2u(__floats2half2_rn(pA8, pA9));
                u32 a3 = h2u(__floats2half2_rn(pB8, pB9));
#pragma unroll
                for (int jp = 0; jp < 4; ++jp) {
                    ldmx4(b, vps + swz(co + jp * 16 + brow, kt * 16 + bcol));
                    mma16816(d[2*jp],   a0, a1, a2, a3, b[0], b[1]);
                    mma16816(d[2*jp+1], a0, a1, a2, a3, b[2], b[3]);
                }
            }
        }
        __syncthreads();                      // BAR5b: AV reads of VPS done

        // ---------- outs (overlay on K'/V') ----------
#pragma unroll
        for (int j = 0; j < 8; ++j) {
            int col = co + j * 8 + q4 * 2;
            if (actA) {
                outs[mA * 129 + col]     = d[j][0];
                outs[mA * 129 + col + 1] = d[j][1];
            }
            if (actB) {
                outs[mB * 129 + col]     = d[j][2];
                outs[mB * 129 + col + 1] = d[j][3];
            }
        }
        __syncthreads();                      // BAR6

        // ---------- coalesced store ----------
        float* ob = out + (size_t)n * (OO * TT * VV) + (size_t)t0 * VV;
        for (int orow = wid; orow < OO; orow += 16) {
            float* dst = ob + (size_t)orow * (TT * VV);
#pragma unroll
            for (int p = 0; p < 4; ++p) {
                int m = lid + p * 32;
                if (m < nvalid) dst[m] = outs[m * 129 + orow];
            }
        }
        // no barrier: next iter's BAR1 separates outs reads from K' rewrite
    }
}

extern "C" void kernel_launch(void* const* d_in, const int* in_sizes, int n_in,
                              void* d_out, int out_size)
{
    const float* x   = (const float*)d_in[0];
    const float* wq  = (const float*)d_in[1];
    const float* bq  = (const float*)d_in[2];
    const float* wk  = (const float*)d_in[3];
    const float* bk  = (const float*)d_in[4];
    const float* wv  = (const float*)d_in[5];
    const float* bv  = (const float*)d_in[6];
    const float* be  = (const float*)d_in[7];
    const int*   hop = (const int*)d_in[8];
    float* out = (float*)d_out;

    int sms = 148;
    cudaDeviceGetAttribute(&sms, cudaDevAttrMultiProcessorCount, 0);

    cudaFuncSetAttribute(phys_attn_pers,
                         cudaFuncAttributeMaxDynamicSharedMemorySize, SMEM_BYTES);

    prep_w<<<(OO * CC + 255) / 256, 256>>>(wq, wk, wv);
    phys_attn_pers<<<sms, THREADS, SMEM_BYTES>>>(
        x, bq, bk, bv, be, hop, out);
}

// round 9
// speedup vs baseline: 1.5594x; 1.4314x over previous
#include <cuda_runtime.h>
#include <cuda_fp16.h>
#include <cstdint>

typedef unsigned int u32;

#define NN 64
#define CC 128
#define TT 256
#define VV 25
#define OO 128
#define TILES 52
#define NITEMS (NN * TILES)
#define THREADS 512
#define SCALE 0.08838834764831845f
#define NEG_INF (-1e30f)

// swizzled fp16 tiles: [128 rows][128 halves], row stride 256B, 16B-chunk XOR
#define WKS_OFF 0
#define WVS_OFF 32768
#define WQB_OFF 65536          // Wq image / Q' overlay
#define XS_OFF  98304          // x tile (streamed by helper warps)
#define KPS_OFF 131072         // K'
#define VPS_OFF 163840         // V'^T
#define OUTS_OFF KPS_OFF       // outs [128][130] f32 overlay (66560B, ends 197632)
#define BT_OFF  209920
#define BQ_OFF  212420
#define BK_OFF  212932
#define BV_OFF  213444
#define SMEM_BYTES 214016

__device__ __half g_wh[3][OO * CC];

__global__ void __launch_bounds__(256) prep_w(
    const float* __restrict__ wq, const float* __restrict__ wk,
    const float* __restrict__ wv)
{
    int i = blockIdx.x * blockDim.x + threadIdx.x;
    if (i < OO * CC) {
        g_wh[0][i] = __float2half_rn(wq[i]);
        g_wh[1][i] = __float2half_rn(wk[i]);
        g_wh[2][i] = __float2half_rn(wv[i]);
    }
}

static __device__ __forceinline__ int swz(int row, int colh) {
    return (row << 8) + ((((colh >> 3) ^ (row & 7))) << 4) + ((colh & 7) << 1);
}
static __device__ __forceinline__ void mma16816(
    float* d, u32 a0, u32 a1, u32 a2, u32 a3, u32 b0, u32 b1)
{
    asm volatile(
        "mma.sync.aligned.m16n8k16.row.col.f32.f16.f16.f32 "
        "{%0,%1,%2,%3}, {%4,%5,%6,%7}, {%8,%9}, {%0,%1,%2,%3};"
        : "+f"(d[0]), "+f"(d[1]), "+f"(d[2]), "+f"(d[3])
        : "r"(a0), "r"(a1), "r"(a2), "r"(a3), "r"(b0), "r"(b1));
}
static __device__ __forceinline__ void ldmx4(u32* r, const void* p) {
    u32 a = (u32)__cvta_generic_to_shared(p);
    asm volatile("ldmatrix.sync.aligned.m8n8.x4.shared.b16 {%0,%1,%2,%3}, [%4];"
        : "=r"(r[0]), "=r"(r[1]), "=r"(r[2]), "=r"(r[3]) : "r"(a));
}
static __device__ __forceinline__ u32 h2u(__half2 h) {
    u32 r; asm("mov.b32 %0, %1;" : "=r"(r) : "r"(*(u32*)&h)); return r;
}
static __device__ __forceinline__ u32 packp(float a, float b) {
    return h2u(__floats2half2_rn(a, b));
}

__global__ void __launch_bounds__(THREADS, 1) phys_attn_pers(
    const float* __restrict__ x,
    const float* __restrict__ bq, const float* __restrict__ bk,
    const float* __restrict__ bv,
    const float* __restrict__ bias_emb, const int* __restrict__ hop,
    float* __restrict__ out)
{
    extern __shared__ __align__(16) char sm[];
    char* wks = sm + WKS_OFF;
    char* wvs = sm + WVS_OFF;
    char* wqb = sm + WQB_OFF;
    char* xs  = sm + XS_OFF;
    char* kps = sm + KPS_OFF;
    char* vps = sm + VPS_OFF;
    float* outs   = (float*)(sm + OUTS_OFF);
    float* bias_s = (float*)(sm + BT_OFF);
    float* bqs    = (float*)(sm + BQ_OFF);
    float* bks    = (float*)(sm + BK_OFF);
    float* bvs    = (float*)(sm + BV_OFF);

    const int tid = threadIdx.x;
    const int wid = tid >> 5, lid = tid & 31;
    const int gr = lid >> 2, q4 = lid & 3;
    const int ms = wid >> 1, half = wid & 1;
    const int m0 = ms * 16;           // projection-phase strip
    const int co = half * 64;

    const int arow = (lid & 7) + ((lid >> 3) & 1) * 8;
    const int acol = ((lid >> 4) & 1) * 8;
    const int brow = (lid & 7) + ((lid >> 4) & 1) * 8;
    const int bcol = ((lid >> 3) & 1) * 8;

    // ---- prologue ----
#pragma unroll
    for (int k = 0; k < 4; ++k) {
        int h0 = tid * 32 + k * 8;
        int off = swz(h0 >> 7, h0 & 127);
        *(uint4*)(wks + off) = *(const uint4*)(&g_wh[1][h0]);
        *(uint4*)(wvs + off) = *(const uint4*)(&g_wh[2][h0]);
    }
    if (tid < OO) {
        bqs[tid] = __ldg(bq + tid);
        bks[tid] = __ldg(bk + tid);
        bvs[tid] = __ldg(bv + tid);
    }
    for (int i = tid; i < VV * VV; i += THREADS)
        bias_s[i] = __ldg(bias_emb + __ldg(hop + i));

    int it = blockIdx.x;
    if (it < NITEMS) {
        int n = it / TILES, tile = it - n * TILES;
        int nval = (tile < 51) ? 125 : 25;
        const float* xb = x + (size_t)n * (CC * TT * VV) + (size_t)(tile * 5) * VV;
#pragma unroll 4
        for (int p = 0; p < 32; ++p) {
            int i = tid + p * THREADS;
            int c = i >> 7, m = i & 127;
            float val = (m < nval) ? __ldg(xb + c * (TT * VV) + m) : 0.f;
            *(__half*)(xs + swz(m, c)) = __float2half_rn(val);
        }
    }
    __syncthreads();

    for (; it < NITEMS; it += gridDim.x) {
        const int n = it / TILES, tile = it - n * TILES;
        const int t0 = tile * 5;
        const int nvalid = (tile < 51) ? 125 : 25;
        const int nit = it + gridDim.x;
        const bool hn = nit < NITEMS;
        int nnval = 0;
        const float* nxb = x;
        if (hn) {
            int nn = nit / TILES, ntile = nit - nn * TILES;
            nnval = (ntile < 51) ? 125 : 25;
            nxb = x + (size_t)nn * (CC * TT * VV) + (size_t)(ntile * 5) * VV;
        }

        // top: cache x A-frags; refill Wq image from L2
        u32 af[8][4];
#pragma unroll
        for (int kt = 0; kt < 8; ++kt)
            ldmx4(af[kt], xs + swz(m0 + arow, kt * 16 + acol));
#pragma unroll
        for (int k = 0; k < 4; ++k) {
            int h0 = tid * 32 + k * 8;
            *(uint4*)(wqb + swz(h0 >> 7, h0 & 127)) = *(const uint4*)(&g_wh[0][h0]);
        }
        __syncthreads();                      // BAR1

        float d[8][4];
        u32 b[4];

        // ---------- K projection -> K' ----------
#pragma unroll
        for (int j = 0; j < 8; ++j) { d[j][0]=d[j][1]=d[j][2]=d[j][3]=0.f; }
#pragma unroll
        for (int kt = 0; kt < 8; ++kt) {
#pragma unroll
            for (int jp = 0; jp < 4; ++jp) {
                ldmx4(b, wks + swz(co + jp * 16 + brow, kt * 16 + bcol));
                mma16816(d[2*jp],   af[kt][0],af[kt][1],af[kt][2],af[kt][3], b[0],b[1]);
                mma16816(d[2*jp+1], af[kt][0],af[kt][1],af[kt][2],af[kt][3], b[2],b[3]);
            }
        }
#pragma unroll
        for (int j = 0; j < 8; ++j) {
            int col = co + j * 8 + q4 * 2;
            float b0 = bks[col], b1 = bks[col + 1];
            *(__half2*)(kps + swz(m0 + gr, col)) =
                __floats2half2_rn(d[j][0] + b0, d[j][1] + b1);
            *(__half2*)(kps + swz(m0 + gr + 8, col)) =
                __floats2half2_rn(d[j][2] + b0, d[j][3] + b1);
        }

        // ---------- V projection -> V'^T ----------
#pragma unroll
        for (int j = 0; j < 8; ++j) { d[j][0]=d[j][1]=d[j][2]=d[j][3]=0.f; }
#pragma unroll
        for (int kt = 0; kt < 8; ++kt) {
#pragma unroll
            for (int jp = 0; jp < 4; ++jp) {
                ldmx4(b, wvs + swz(co + jp * 16 + brow, kt * 16 + bcol));
                mma16816(d[2*jp],   af[kt][0],af[kt][1],af[kt][2],af[kt][3], b[0],b[1]);
                mma16816(d[2*jp+1], af[kt][0],af[kt][1],af[kt][2],af[kt][3], b[2],b[3]);
            }
        }
#pragma unroll
        for (int j = 0; j < 8; ++j) {
            int col = co + j * 8 + q4 * 2;
            float b0 = bvs[col], b1 = bvs[col + 1];
            *(__half*)(vps + swz(col,     m0 + gr))     = __float2half_rn(d[j][0] + b0);
            *(__half*)(vps + swz(col + 1, m0 + gr))     = __float2half_rn(d[j][1] + b1);
            *(__half*)(vps + swz(col,     m0 + gr + 8)) = __float2half_rn(d[j][2] + b0);
            *(__half*)(vps + swz(col + 1, m0 + gr + 8)) = __float2half_rn(d[j][3] + b1);
        }

        // ---------- Q projection (reads wqb) ----------
#pragma unroll
        for (int j = 0; j < 8; ++j) { d[j][0]=d[j][1]=d[j][2]=d[j][3]=0.f; }
#pragma unroll
        for (int kt = 0; kt < 8; ++kt) {
#pragma unroll
            for (int jp = 0; jp < 4; ++jp) {
                ldmx4(b, wqb + swz(co + jp * 16 + brow, kt * 16 + bcol));
                mma16816(d[2*jp],   af[kt][0],af[kt][1],af[kt][2],af[kt][3], b[0],b[1]);
                mma16816(d[2*jp+1], af[kt][0],af[kt][1],af[kt][2],af[kt][3], b[2],b[3]);
            }
        }
        __syncthreads();                      // BAR2: wqb readers done
#pragma unroll
        for (int j = 0; j < 8; ++j) {         // Q' (+bq) -> wqb
            int col = co + j * 8 + q4 * 2;
            float b0 = bqs[col], b1 = bqs[col + 1];
            *(__half2*)(wqb + swz(m0 + gr, col)) =
                __floats2half2_rn(d[j][0] + b0, d[j][1] + b1);
            *(__half2*)(wqb + swz(m0 + gr + 8, col)) =
                __floats2half2_rn(d[j][2] + b0, d[j][3] + b1);
        }
        __syncthreads();                      // BAR3: Q'/K'/V' visible

        float acc[16][4];
        int sm0 = wid * 16;
        bool wact = (wid < 8) && (sm0 < nvalid);
        int mA = sm0 + gr, mB = mA + 8;
        bool actA = false, actB = false;
        int loA = 0, loB = 0;

        if (wid < 8) {
            // ======== strip warps: S -> softmax -> P -> AV, all in regs ========
            actA = mA < nvalid; actB = mB < nvalid;
            loA = (mA / VV) * VV; loB = (mB / VV) * VV;
            const int vlA = mA - loA, vlB = mB - loB;
            int jlo = 0, ktlo = 0, kthi = 0, dlt = 0;
            if (wact) {
                int rhi = min(sm0 + 16, nvalid);
                int wlo = (sm0 / VV) * VV;
                int whi = min(((rhi - 1) / VV) * VV + VV, nvalid);
                jlo = wlo >> 3; ktlo = wlo >> 4; kthi = (whi + 15) >> 4;
                dlt = 2 * ktlo - jlo;          // 0 or -1
            }
            float d2[7][4];
#pragma unroll
            for (int jt = 0; jt < 7; ++jt)
                d2[jt][0] = d2[jt][1] = d2[jt][2] = d2[jt][3] = 0.f;

            if (wact) {
#pragma unroll
                for (int kt = 0; kt < 8; ++kt) {
                    u32 a[4];
                    ldmx4(a, wqb + swz(sm0 + arow, kt * 16 + acol));
#pragma unroll
                    for (int jt = 0; jt < 7; ++jt) {
                        int nrow = (jlo + jt) * 8 + gr;
                        int rb = nrow << 8;
                        u32 b0 = *(const u32*)(kps + rb +
                                  (((2 * kt) ^ (nrow & 7)) << 4) + (q4 << 2));
                        u32 b1 = *(const u32*)(kps + rb +
                                  (((2 * kt + 1) ^ (nrow & 7)) << 4) + (q4 << 2));
                        mma16816(d2[jt], a[0], a[1], a[2], a[3], b0, b1);
                    }
                }
            }
            // softmax in registers
            float mxA = NEG_INF, mxB = NEG_INF;
#pragma unroll
            for (int jt = 0; jt < 7; ++jt) {
                int c0 = (jlo + jt) * 8 + q4 * 2;
                int rA = c0 - loA, rB = c0 - loB;
                float v;
                v = (actA && rA >= 0 && rA < VV)
                    ? fmaf(d2[jt][0], SCALE, bias_s[vlA * VV + rA]) : NEG_INF;
                d2[jt][0] = v; mxA = fmaxf(mxA, v);
                v = (actA && rA + 1 >= 0 && rA + 1 < VV)
                    ? fmaf(d2[jt][1], SCALE, bias_s[vlA * VV + rA + 1]) : NEG_INF;
                d2[jt][1] = v; mxA = fmaxf(mxA, v);
                v = (actB && rB >= 0 && rB < VV)
                    ? fmaf(d2[jt][2], SCALE, bias_s[vlB * VV + rB]) : NEG_INF;
                d2[jt][2] = v; mxB = fmaxf(mxB, v);
                v = (actB && rB + 1 >= 0 && rB + 1 < VV)
                    ? fmaf(d2[jt][3], SCALE, bias_s[vlB * VV + rB + 1]) : NEG_INF;
                d2[jt][3] = v; mxB = fmaxf(mxB, v);
            }
            mxA = fmaxf(mxA, __shfl_xor_sync(0xffffffffu, mxA, 1));
            mxA = fmaxf(mxA, __shfl_xor_sync(0xffffffffu, mxA, 2));
            mxB = fmaxf(mxB, __shfl_xor_sync(0xffffffffu, mxB, 1));
            mxB = fmaxf(mxB, __shfl_xor_sync(0xffffffffu, mxB, 2));
            float smA = 0.f, smB = 0.f;
#pragma unroll
            for (int jt = 0; jt < 7; ++jt) {
                float e0 = (d2[jt][0] > NEG_INF * 0.5f) ? __expf(d2[jt][0] - mxA) : 0.f;
                float e1 = (d2[jt][1] > NEG_INF * 0.5f) ? __expf(d2[jt][1] - mxA) : 0.f;
                float e2 = (d2[jt][2] > NEG_INF * 0.5f) ? __expf(d2[jt][2] - mxB) : 0.f;
                float e3 = (d2[jt][3] > NEG_INF * 0.5f) ? __expf(d2[jt][3] - mxB) : 0.f;
                d2[jt][0] = e0; d2[jt][1] = e1; d2[jt][2] = e2; d2[jt][3] = e3;
                smA += e0 + e1; smB += e2 + e3;
            }
            smA += __shfl_xor_sync(0xffffffffu, smA, 1);
            smA += __shfl_xor_sync(0xffffffffu, smA, 2);
            smB += __shfl_xor_sync(0xffffffffu, smB, 1);
            smB += __shfl_xor_sync(0xffffffffu, smB, 2);
            float ivA = (smA > 0.f) ? (1.f / smA) : 0.f;
            float ivB = (smB > 0.f) ? (1.f / smB) : 0.f;

            // pack P fragments: S accumulator layout == AV A-fragment layout
            u32 pa0[4], pa1[4], pa2[4], pa3[4];
#pragma unroll
            for (int kr = 0; kr < 4; ++kr) { pa0[kr]=pa1[kr]=pa2[kr]=pa3[kr]=0u; }
            if (dlt == 0) {
#pragma unroll
                for (int kr = 0; kr < 4; ++kr) {
                    if (ktlo + kr < kthi) {
                        pa0[kr] = packp(d2[2*kr][0]*ivA, d2[2*kr][1]*ivA);
                        pa1[kr] = packp(d2[2*kr][2]*ivB, d2[2*kr][3]*ivB);
                        if (2*kr + 1 < 7) {
                            pa2[kr] = packp(d2[2*kr+1][0]*ivA, d2[2*kr+1][1]*ivA);
                            pa3[kr] = packp(d2[2*kr+1][2]*ivB, d2[2*kr+1][3]*ivB);
                        }
                    }
                }
            } else {
#pragma unroll
                for (int kr = 0; kr < 4; ++kr) {
                    if (ktlo + kr < kthi) {
                        if (2*kr - 1 >= 0) {
                            pa0[kr] = packp(d2[2*kr-1][0]*ivA, d2[2*kr-1][1]*ivA);
                            pa1[kr] = packp(d2[2*kr-1][2]*ivB, d2[2*kr-1][3]*ivB);
                        }
                        pa2[kr] = packp(d2[2*kr][0]*ivA, d2[2*kr][1]*ivA);
                        pa3[kr] = packp(d2[2*kr][2]*ivB, d2[2*kr][3]*ivB);
                    }
                }
            }

            // AV = P V'  (full 128 out cols, windowed k-tiles)
#pragma unroll
            for (int np = 0; np < 16; ++np)
                acc[np][0] = acc[np][1] = acc[np][2] = acc[np][3] = 0.f;
            if (wact) {
#pragma unroll
                for (int kr = 0; kr < 4; ++kr) {
                    if (ktlo + kr < kthi) {
                        int ktv = ktlo + kr;
#pragma unroll
                        for (int jp = 0; jp < 8; ++jp) {
                            ldmx4(b, vps + swz(jp * 16 + brow, ktv * 16 + bcol));
                            mma16816(acc[2*jp],   pa0[kr],pa1[kr],pa2[kr],pa3[kr], b[0],b[1]);
                            mma16816(acc[2*jp+1], pa0[kr],pa1[kr],pa2[kr],pa3[kr], b[2],b[3]);
                        }
                    }
                }
            }
        } else {
            // ======== helper warps: stage next item's x ========
            if (hn) {
                int ht = tid - 256;
                int m = ht & 127;
                int c2b = ht >> 7;
                bool mv = m < nnval;
                const float* src = nxb + m;
#pragma unroll 4
                for (int p = 0; p < 32; ++p) {
                    int c2 = c2b + 2 * p;
                    float v0 = mv ? __ldg(src + (2 * c2) * (TT * VV)) : 0.f;
                    float v1 = mv ? __ldg(src + (2 * c2 + 1) * (TT * VV)) : 0.f;
                    *(__half2*)(xs + swz(m, 2 * c2)) = __floats2half2_rn(v0, v1);
                }
            }
        }
        __syncthreads();                      // BAR_PREOUT: all kps/vps reads done

        // outs STS (strip warps; overlays K'/V')
        if (wid < 8) {
#pragma unroll
            for (int np = 0; np < 16; ++np) {
                int col = np * 8 + q4 * 2;
                if (actA) *(float2*)(&outs[mA * 130 + col]) =
                    make_float2(acc[np][0], acc[np][1]);
                if (actB) *(float2*)(&outs[mB * 130 + col]) =
                    make_float2(acc[np][2], acc[np][3]);
            }
        }
        __syncthreads();                      // BAR6

        // coalesced store
        float* ob = out + (size_t)n * (OO * TT * VV) + (size_t)t0 * VV;
        for (int orow = wid; orow < OO; orow += 16) {
            float* dst = ob + (size_t)orow * (TT * VV);
#pragma unroll
            for (int p = 0; p < 4; ++p) {
                int m = lid + p * 32;
                if (m < nvalid) dst[m] = outs[m * 130 + orow];
            }
        }
        // next iter's BAR1 orders outs reads vs K' rewrite
    }
}

extern "C" void kernel_launch(void* const* d_in, const int* in_sizes, int n_in,
                              void* d_out, int out_size)
{
    const float* x   = (const float*)d_in[0];
    const float* wq  = (const float*)d_in[1];
    const float* bq  = (const float*)d_in[2];
    const float* wk  = (const float*)d_in[3];
    const float* bk  = (const float*)d_in[4];
    const float* wv  = (const float*)d_in[5];
    const float* bv  = (const float*)d_in[6];
    const float* be  = (const float*)d_in[7];
    const int*   hop = (const int*)d_in[8];
    float* out = (float*)d_out;

    int sms = 148;
    cudaDeviceGetAttribute(&sms, cudaDevAttrMultiProcessorCount, 0);

    cudaFuncSetAttribute(phys_attn_pers,
                         cudaFuncAttributeMaxDynamicSharedMemorySize, SMEM_BYTES);

    prep_w<<<(OO * CC + 255) / 256, 256>>>(wq, wk, wv);
    phys_attn_pers<<<sms, THREADS, SMEM_BYTES>>>(
        x, bq, bk, bv, be, hop, out);
}

// round 10
// speedup vs baseline: 1.5602x; 1.0005x over previous
#include <cuda_runtime.h>
#include <cuda_fp16.h>
#include <cstdint>

typedef unsigned int u32;

#define NN 64
#define CC 128
#define TT 256
#define VV 25
#define OO 128
#define TILES 52
#define NITEMS (NN * TILES)
#define THREADS 512
#define SCALE 0.08838834764831845f
#define NEG_INF (-1e30f)

// swizzled fp16 tiles: [128 rows][128 halves], row stride 256B, 16B-chunk XOR
#define WKS_OFF 0
#define WVS_OFF 32768
#define WQB_OFF 65536          // Wq image / Q' overlay
#define XS_OFF  98304          // x tile (register-prefetched)
#define KPS_OFF 131072         // K'
#define VPS_OFF 163840         // V' [m][o]
#define OUTS_OFF KPS_OFF       // outs [128][130] f32 overlay
#define BT_OFF  209920
#define BQ_OFF  212420
#define BK_OFF  212932
#define BV_OFF  213444
#define SMEM_BYTES 214016

__device__ __half g_wh[3][OO * CC];

__global__ void __launch_bounds__(256) prep_w(
    const float* __restrict__ wq, const float* __restrict__ wk,
    const float* __restrict__ wv)
{
    int i = blockIdx.x * blockDim.x + threadIdx.x;
    if (i < OO * CC) {
        g_wh[0][i] = __float2half_rn(wq[i]);
        g_wh[1][i] = __float2half_rn(wk[i]);
        g_wh[2][i] = __float2half_rn(wv[i]);
    }
}

static __device__ __forceinline__ int swz(int row, int colh) {
    return (row << 8) + ((((colh >> 3) ^ (row & 7))) << 4) + ((colh & 7) << 1);
}
static __device__ __forceinline__ void mma16816(
    float* d, u32 a0, u32 a1, u32 a2, u32 a3, u32 b0, u32 b1)
{
    asm volatile(
        "mma.sync.aligned.m16n8k16.row.col.f32.f16.f16.f32 "
        "{%0,%1,%2,%3}, {%4,%5,%6,%7}, {%8,%9}, {%0,%1,%2,%3};"
        : "+f"(d[0]), "+f"(d[1]), "+f"(d[2]), "+f"(d[3])
        : "r"(a0), "r"(a1), "r"(a2), "r"(a3), "r"(b0), "r"(b1));
}
static __device__ __forceinline__ void ldmx4(u32* r, const void* p) {
    u32 a = (u32)__cvta_generic_to_shared(p);
    asm volatile("ldmatrix.sync.aligned.m8n8.x4.shared.b16 {%0,%1,%2,%3}, [%4];"
        : "=r"(r[0]), "=r"(r[1]), "=r"(r[2]), "=r"(r[3]) : "r"(a));
}
static __device__ __forceinline__ void ldmx4t(u32* r, const void* p) {
    u32 a = (u32)__cvta_generic_to_shared(p);
    asm volatile("ldmatrix.sync.aligned.m8n8.x4.trans.shared.b16 {%0,%1,%2,%3}, [%4];"
        : "=r"(r[0]), "=r"(r[1]), "=r"(r[2]), "=r"(r[3]) : "r"(a));
}
static __device__ __forceinline__ u32 h2u(__half2 h) {
    u32 r; asm("mov.b32 %0, %1;" : "=r"(r) : "r"(*(u32*)&h)); return r;
}
static __device__ __forceinline__ u32 packp(float a, float b) {
    return h2u(__floats2half2_rn(a, b));
}

__global__ void __launch_bounds__(THREADS, 1) phys_attn_pers(
    const float* __restrict__ x,
    const float* __restrict__ bq, const float* __restrict__ bk,
    const float* __restrict__ bv,
    const float* __restrict__ bias_emb, const int* __restrict__ hop,
    float* __restrict__ out)
{
    extern __shared__ __align__(16) char sm[];
    char* wks = sm + WKS_OFF;
    char* wvs = sm + WVS_OFF;
    char* wqb = sm + WQB_OFF;
    char* xs  = sm + XS_OFF;
    char* kps = sm + KPS_OFF;
    char* vps = sm + VPS_OFF;
    float* outs   = (float*)(sm + OUTS_OFF);
    float* bias_s = (float*)(sm + BT_OFF);
    float* bqs    = (float*)(sm + BQ_OFF);
    float* bks    = (float*)(sm + BK_OFF);
    float* bvs    = (float*)(sm + BV_OFF);

    const int tid = threadIdx.x;
    const int wid = tid >> 5, lid = tid & 31;
    const int gr = lid >> 2, q4 = lid & 3;
    const int m0 = (wid >> 1) * 16;      // strip rows (proj AND S/AV)
    const int co = (wid & 1) * 64;       // proj col half; also AV col half

    const int arow = (lid & 7) + ((lid >> 3) & 1) * 8;
    const int acol = ((lid >> 4) & 1) * 8;
    const int brow = (lid & 7) + ((lid >> 4) & 1) * 8;
    const int bcol = ((lid >> 3) & 1) * 8;
    const int vrow = lid & 15;                 // trans-B: k rows
    const int vcs  = ((lid >> 4) & 1) * 8;     // trans-B: col select

    // ---- prologue ----
#pragma unroll
    for (int k = 0; k < 4; ++k) {
        int h0 = tid * 32 + k * 8;
        int off = swz(h0 >> 7, h0 & 127);
        *(uint4*)(wks + off) = *(const uint4*)(&g_wh[1][h0]);
        *(uint4*)(wvs + off) = *(const uint4*)(&g_wh[2][h0]);
    }
    if (tid < OO) {
        bqs[tid] = __ldg(bq + tid);
        bks[tid] = __ldg(bk + tid);
        bvs[tid] = __ldg(bv + tid);
    }
    for (int i = tid; i < VV * VV; i += THREADS)
        bias_s[i] = __ldg(bias_emb + __ldg(hop + i));

    int it = blockIdx.x;
    if (it < NITEMS) {
        int n = it / TILES, tile = it - n * TILES;
        int nval = (tile < 51) ? 125 : 25;
        const float* xb = x + (size_t)n * (CC * TT * VV) + (size_t)(tile * 5) * VV;
#pragma unroll 4
        for (int p = 0; p < 32; ++p) {
            int i = tid + p * THREADS;
            int c = i >> 7, m = i & 127;
            float val = (m < nval) ? __ldg(xb + c * (TT * VV) + m) : 0.f;
            *(__half*)(xs + swz(m, c)) = __float2half_rn(val);
        }
    }
    __syncthreads();

    for (; it < NITEMS; it += gridDim.x) {
        const int n = it / TILES, tile = it - n * TILES;
        const int t0 = tile * 5;
        const int nvalid = (tile < 51) ? 125 : 25;
        const int nit = it + gridDim.x;
        const bool hn = nit < NITEMS;
        int nnval = 0;
        const float* nxb = x;
        if (hn) {
            int nn = nit / TILES, ntile = nit - nn * TILES;
            nnval = (ntile < 51) ? 125 : 25;
            nxb = x + (size_t)nn * (CC * TT * VV) + (size_t)(ntile * 5) * VV;
        }

        // top: cache x A-frags; refill Wq image from L2
        u32 af[8][4];
#pragma unroll
        for (int kt = 0; kt < 8; ++kt)
            ldmx4(af[kt], xs + swz(m0 + arow, kt * 16 + acol));
#pragma unroll
        for (int k = 0; k < 4; ++k) {
            int h0 = tid * 32 + k * 8;
            *(uint4*)(wqb + swz(h0 >> 7, h0 & 127)) = *(const uint4*)(&g_wh[0][h0]);
        }
        __syncthreads();                      // BAR1

        float d[8][4];
        u32 b[4];
        float xr[16];

        // prefetch chunk1 LDG (overlaps K projection)
        if (hn) {
#pragma unroll
            for (int p = 0; p < 16; ++p) {
                int i = tid + p * THREADS;
                int c = i >> 7, m = i & 127;
                xr[p] = (m < nnval) ? __ldg(nxb + c * (TT * VV) + m) : 0.f;
            }
        }

        // ---------- K projection -> K' ----------
#pragma unroll
        for (int j = 0; j < 8; ++j) { d[j][0]=d[j][1]=d[j][2]=d[j][3]=0.f; }
#pragma unroll
        for (int kt = 0; kt < 8; ++kt) {
#pragma unroll
            for (int jp = 0; jp < 4; ++jp) {
                ldmx4(b, wks + swz(co + jp * 16 + brow, kt * 16 + bcol));
                mma16816(d[2*jp],   af[kt][0],af[kt][1],af[kt][2],af[kt][3], b[0],b[1]);
                mma16816(d[2*jp+1], af[kt][0],af[kt][1],af[kt][2],af[kt][3], b[2],b[3]);
            }
        }
#pragma unroll
        for (int j = 0; j < 8; ++j) {
            int col = co + j * 8 + q4 * 2;
            float b0 = bks[col], b1 = bks[col + 1];
            *(__half2*)(kps + swz(m0 + gr, col)) =
                __floats2half2_rn(d[j][0] + b0, d[j][1] + b1);
            *(__half2*)(kps + swz(m0 + gr + 8, col)) =
                __floats2half2_rn(d[j][2] + b0, d[j][3] + b1);
        }
        // chunk1 STS + chunk2 LDG
        if (hn) {
#pragma unroll
            for (int p = 0; p < 16; ++p) {
                int i = tid + p * THREADS;
                *(__half*)(xs + swz(i & 127, i >> 7)) = __float2half_rn(xr[p]);
            }
#pragma unroll
            for (int p = 0; p < 16; ++p) {
                int i = tid + (p + 16) * THREADS;
                int c = i >> 7, m = i & 127;
                xr[p] = (m < nnval) ? __ldg(nxb + c * (TT * VV) + m) : 0.f;
            }
        }

        // ---------- V projection -> V' [m][o] ----------
#pragma unroll
        for (int j = 0; j < 8; ++j) { d[j][0]=d[j][1]=d[j][2]=d[j][3]=0.f; }
#pragma unroll
        for (int kt = 0; kt < 8; ++kt) {
#pragma unroll
            for (int jp = 0; jp < 4; ++jp) {
                ldmx4(b, wvs + swz(co + jp * 16 + brow, kt * 16 + bcol));
                mma16816(d[2*jp],   af[kt][0],af[kt][1],af[kt][2],af[kt][3], b[0],b[1]);
                mma16816(d[2*jp+1], af[kt][0],af[kt][1],af[kt][2],af[kt][3], b[2],b[3]);
            }
        }
#pragma unroll
        for (int j = 0; j < 8; ++j) {
            int col = co + j * 8 + q4 * 2;
            float b0 = bvs[col], b1 = bvs[col + 1];
            *(__half2*)(vps + swz(m0 + gr, col)) =
                __floats2half2_rn(d[j][0] + b0, d[j][1] + b1);
            *(__half2*)(vps + swz(m0 + gr + 8, col)) =
                __floats2half2_rn(d[j][2] + b0, d[j][3] + b1);
        }
        // chunk2 STS
        if (hn) {
#pragma unroll
            for (int p = 0; p < 16; ++p) {
                int i = tid + (p + 16) * THREADS;
                *(__half*)(xs + swz(i & 127, i >> 7)) = __float2half_rn(xr[p]);
            }
        }

        // ---------- Q projection (reads wqb) ----------
#pragma unroll
        for (int j = 0; j < 8; ++j) { d[j][0]=d[j][1]=d[j][2]=d[j][3]=0.f; }
#pragma unroll
        for (int kt = 0; kt < 8; ++kt) {
#pragma unroll
            for (int jp = 0; jp < 4; ++jp) {
                ldmx4(b, wqb + swz(co + jp * 16 + brow, kt * 16 + bcol));
                mma16816(d[2*jp],   af[kt][0],af[kt][1],af[kt][2],af[kt][3], b[0],b[1]);
                mma16816(d[2*jp+1], af[kt][0],af[kt][1],af[kt][2],af[kt][3], b[2],b[3]);
            }
        }
        __syncthreads();                      // BAR2
#pragma unroll
        for (int j = 0; j < 8; ++j) {         // Q' (+bq) -> wqb
            int col = co + j * 8 + q4 * 2;
            float b0 = bqs[col], b1 = bqs[col + 1];
            *(__half2*)(wqb + swz(m0 + gr, col)) =
                __floats2half2_rn(d[j][0] + b0, d[j][1] + b1);
            *(__half2*)(wqb + swz(m0 + gr + 8, col)) =
                __floats2half2_rn(d[j][2] + b0, d[j][3] + b1);
        }
        __syncthreads();                      // BAR3: Q'/K'/V' visible

        // ======== S -> softmax -> AV: all 16 warps (pairs share a strip) =====
        const bool wact = m0 < nvalid;
        const int mA = m0 + gr, mB = mA + 8;
        const bool actA = mA < nvalid, actB = mB < nvalid;
        const int loA = (mA / VV) * VV, loB = (mB / VV) * VV;
        const int vlA = mA - loA, vlB = mB - loB;
        int jlo = 0, ktlo = 0, kthi = 0, dlt = 0;
        if (wact) {
            int rhi = min(m0 + 16, nvalid);
            int wlo = (m0 / VV) * VV;
            int whi = min(((rhi - 1) / VV) * VV + VV, nvalid);
            jlo = wlo >> 3; ktlo = wlo >> 4; kthi = (whi + 15) >> 4;
            dlt = 2 * ktlo - jlo;
        }
        float d2[7][4];
#pragma unroll
        for (int jt = 0; jt < 7; ++jt)
            d2[jt][0] = d2[jt][1] = d2[jt][2] = d2[jt][3] = 0.f;

        if (wact) {
#pragma unroll
            for (int kt = 0; kt < 8; ++kt) {
                u32 a[4];
                ldmx4(a, wqb + swz(m0 + arow, kt * 16 + acol));
#pragma unroll
                for (int jt = 0; jt < 7; ++jt) {
                    int nrow = (jlo + jt) * 8 + gr;
                    int rb = nrow << 8;
                    u32 b0 = *(const u32*)(kps + rb +
                              (((2 * kt) ^ (nrow & 7)) << 4) + (q4 << 2));
                    u32 b1 = *(const u32*)(kps + rb +
                              (((2 * kt + 1) ^ (nrow & 7)) << 4) + (q4 << 2));
                    mma16816(d2[jt], a[0], a[1], a[2], a[3], b0, b1);
                }
            }
        }
        // register softmax
        float mxA = NEG_INF, mxB = NEG_INF;
#pragma unroll
        for (int jt = 0; jt < 7; ++jt) {
            int c0 = (jlo + jt) * 8 + q4 * 2;
            int rA = c0 - loA, rB = c0 - loB;
            float v;
            v = (actA && rA >= 0 && rA < VV)
                ? fmaf(d2[jt][0], SCALE, bias_s[vlA * VV + rA]) : NEG_INF;
            d2[jt][0] = v; mxA = fmaxf(mxA, v);
            v = (actA && rA + 1 >= 0 && rA + 1 < VV)
                ? fmaf(d2[jt][1], SCALE, bias_s[vlA * VV + rA + 1]) : NEG_INF;
            d2[jt][1] = v; mxA = fmaxf(mxA, v);
            v = (actB && rB >= 0 && rB < VV)
                ? fmaf(d2[jt][2], SCALE, bias_s[vlB * VV + rB]) : NEG_INF;
            d2[jt][2] = v; mxB = fmaxf(mxB, v);
            v = (actB && rB + 1 >= 0 && rB + 1 < VV)
                ? fmaf(d2[jt][3], SCALE, bias_s[vlB * VV + rB + 1]) : NEG_INF;
            d2[jt][3] = v; mxB = fmaxf(mxB, v);
        }
        mxA = fmaxf(mxA, __shfl_xor_sync(0xffffffffu, mxA, 1));
        mxA = fmaxf(mxA, __shfl_xor_sync(0xffffffffu, mxA, 2));
        mxB = fmaxf(mxB, __shfl_xor_sync(0xffffffffu, mxB, 1));
        mxB = fmaxf(mxB, __shfl_xor_sync(0xffffffffu, mxB, 2));
        float smA = 0.f, smB = 0.f;
#pragma unroll
        for (int jt = 0; jt < 7; ++jt) {
            float e0 = (d2[jt][0] > NEG_INF * 0.5f) ? __expf(d2[jt][0] - mxA) : 0.f;
            float e1 = (d2[jt][1] > NEG_INF * 0.5f) ? __expf(d2[jt][1] - mxA) : 0.f;
            float e2 = (d2[jt][2] > NEG_INF * 0.5f) ? __expf(d2[jt][2] - mxB) : 0.f;
            float e3 = (d2[jt][3] > NEG_INF * 0.5f) ? __expf(d2[jt][3] - mxB) : 0.f;
            d2[jt][0] = e0; d2[jt][1] = e1; d2[jt][2] = e2; d2[jt][3] = e3;
            smA += e0 + e1; smB += e2 + e3;
        }
        smA += __shfl_xor_sync(0xffffffffu, smA, 1);
        smA += __shfl_xor_sync(0xffffffffu, smA, 2);
        smB += __shfl_xor_sync(0xffffffffu, smB, 1);
        smB += __shfl_xor_sync(0xffffffffu, smB, 2);
        float ivA = (smA > 0.f) ? (1.f / smA) : 0.f;
        float ivB = (smB > 0.f) ? (1.f / smB) : 0.f;

        // pack P fragments (S acc layout == AV A-frag layout)
        u32 pa0[4], pa1[4], pa2[4], pa3[4];
#pragma unroll
        for (int kr = 0; kr < 4; ++kr) { pa0[kr]=pa1[kr]=pa2[kr]=pa3[kr]=0u; }
        if (dlt == 0) {
#pragma unroll
            for (int kr = 0; kr < 4; ++kr) {
                if (ktlo + kr < kthi) {
                    pa0[kr] = packp(d2[2*kr][0]*ivA, d2[2*kr][1]*ivA);
                    pa1[kr] = packp(d2[2*kr][2]*ivB, d2[2*kr][3]*ivB);
                    if (2*kr + 1 < 7) {
                        pa2[kr] = packp(d2[2*kr+1][0]*ivA, d2[2*kr+1][1]*ivA);
                        pa3[kr] = packp(d2[2*kr+1][2]*ivB, d2[2*kr+1][3]*ivB);
                    }
                }
            }
        } else {
#pragma unroll
            for (int kr = 0; kr < 4; ++kr) {
                if (ktlo + kr < kthi) {
                    if (2*kr - 1 >= 0) {
                        pa0[kr] = packp(d2[2*kr-1][0]*ivA, d2[2*kr-1][1]*ivA);
                        pa1[kr] = packp(d2[2*kr-1][2]*ivB, d2[2*kr-1][3]*ivB);
                    }
                    pa2[kr] = packp(d2[2*kr][0]*ivA, d2[2*kr][1]*ivA);
                    pa3[kr] = packp(d2[2*kr][2]*ivB, d2[2*kr][3]*ivB);
                }
            }
        }

        // AV = P V' : this warp's col half only (64 cols)
        float acc[8][4];
#pragma unroll
        for (int np = 0; np < 8; ++np)
            acc[np][0] = acc[np][1] = acc[np][2] = acc[np][3] = 0.f;
        if (wact) {
#pragma unroll
            for (int kr = 0; kr < 4; ++kr) {
                if (ktlo + kr < kthi) {
                    int ktv = ktlo + kr;
#pragma unroll
                    for (int jpp = 0; jpp < 4; ++jpp) {
                        int n0 = co + jpp * 16;
                        ldmx4t(b, vps + swz(ktv * 16 + vrow, n0 + vcs));
                        mma16816(acc[2*jpp],   pa0[kr],pa1[kr],pa2[kr],pa3[kr], b[0],b[1]);
                        mma16816(acc[2*jpp+1], pa0[kr],pa1[kr],pa2[kr],pa3[kr], b[2],b[3]);
                    }
                }
            }
        }
        __syncthreads();                      // BAR_PREOUT: kps/vps reads done

        // outs STS (overlays K'/V')
        if (wact) {
#pragma unroll
            for (int np = 0; np < 8; ++np) {
                int col = co + np * 8 + q4 * 2;
                if (actA) *(float2*)(&outs[mA * 130 + col]) =
                    make_float2(acc[np][0], acc[np][1]);
                if (actB) *(float2*)(&outs[mB * 130 + col]) =
                    make_float2(acc[np][2], acc[np][3]);
            }
        }
        __syncthreads();                      // BAR6

        // coalesced store
        float* ob = out + (size_t)n * (OO * TT * VV) + (size_t)t0 * VV;
        for (int orow = wid; orow < OO; orow += 16) {
            float* dst = ob + (size_t)orow * (TT * VV);
#pragma unroll
            for (int p = 0; p < 4; ++p) {
                int m = lid + p * 32;
                if (m < nvalid) dst[m] = outs[m * 130 + orow];
            }
        }
        // next iter's BAR1 orders outs reads vs K' rewrite
    }
}

extern "C" void kernel_launch(void* const* d_in, const int* in_sizes, int n_in,
                              void* d_out, int out_size)
{
    const float* x   = (const float*)d_in[0];
    const float* wq  = (const float*)d_in[1];
    const float* bq  = (const float*)d_in[2];
    const float* wk  = (const float*)d_in[3];
    const float* bk  = (const float*)d_in[4];
    const float* wv  = (const float*)d_in[5];
    const float* bv  = (const float*)d_in[6];
    const float* be  = (const float*)d_in[7];
    const int*   hop = (const int*)d_in[8];
    float* out = (float*)d_out;

    int sms = 148;
    cudaDeviceGetAttribute(&sms, cudaDevAttrMultiProcessorCount, 0);

    cudaFuncSetAttribute(phys_attn_pers,
                         cudaFuncAttributeMaxDynamicSharedMemorySize, SMEM_BYTES);

    prep_w<<<(OO * CC + 255) / 256, 256>>>(wq, wk, wv);
    phys_attn_pers<<<sms, THREADS, SMEM_BYTES>>>(
        x, bq, bk, bv, be, hop, out);
}

// round 11
// speedup vs baseline: 1.7262x; 1.1064x over previous
#include <cuda_runtime.h>
#include <cuda_fp16.h>
#include <cstdint>

typedef unsigned int u32;

#define NN 64
#define CC 128
#define TT 256
#define VV 25
#define OO 128
#define TILES 52
#define NITEMS (NN * TILES)
#define THREADS 512
#define SCALE 0.08838834764831845f
#define NEG_INF (-1e30f)

// swizzled fp16 tiles: [128 rows][128 halves], row stride 256B, 16B-chunk XOR
#define WKS_OFF 0
#define WVS_OFF 32768
#define WQB_OFF 65536          // Wq image / Q' overlay
#define XS_OFF  98304          // x tile (register-prefetched)
#define KPS_OFF 131072         // K'
#define VPS_OFF 163840         // V' [m][o]
#define BT_OFF  196608         // bias table [25][25] f32
#define BQ_OFF  199108
#define BK_OFF  199620
#define BV_OFF  200132
#define SMEM_BYTES 200704

__device__ __half g_wh[3][OO * CC];

__global__ void __launch_bounds__(256) prep_w(
    const float* __restrict__ wq, const float* __restrict__ wk,
    const float* __restrict__ wv)
{
    int i = blockIdx.x * blockDim.x + threadIdx.x;
    if (i < OO * CC) {
        g_wh[0][i] = __float2half_rn(wq[i]);
        g_wh[1][i] = __float2half_rn(wk[i]);
        g_wh[2][i] = __float2half_rn(wv[i]);
    }
}

static __device__ __forceinline__ int swz(int row, int colh) {
    return (row << 8) + ((((colh >> 3) ^ (row & 7))) << 4) + ((colh & 7) << 1);
}
static __device__ __forceinline__ void mma16816(
    float* d, u32 a0, u32 a1, u32 a2, u32 a3, u32 b0, u32 b1)
{
    asm volatile(
        "mma.sync.aligned.m16n8k16.row.col.f32.f16.f16.f32 "
        "{%0,%1,%2,%3}, {%4,%5,%6,%7}, {%8,%9}, {%0,%1,%2,%3};"
        : "+f"(d[0]), "+f"(d[1]), "+f"(d[2]), "+f"(d[3])
        : "r"(a0), "r"(a1), "r"(a2), "r"(a3), "r"(b0), "r"(b1));
}
static __device__ __forceinline__ void ldmx4(u32* r, const void* p) {
    u32 a = (u32)__cvta_generic_to_shared(p);
    asm volatile("ldmatrix.sync.aligned.m8n8.x4.shared.b16 {%0,%1,%2,%3}, [%4];"
        : "=r"(r[0]), "=r"(r[1]), "=r"(r[2]), "=r"(r[3]) : "r"(a));
}
static __device__ __forceinline__ void ldmx4t(u32* r, const void* p) {
    u32 a = (u32)__cvta_generic_to_shared(p);
    asm volatile("ldmatrix.sync.aligned.m8n8.x4.trans.shared.b16 {%0,%1,%2,%3}, [%4];"
        : "=r"(r[0]), "=r"(r[1]), "=r"(r[2]), "=r"(r[3]) : "r"(a));
}
static __device__ __forceinline__ u32 h2u(__half2 h) {
    u32 r; asm("mov.b32 %0, %1;" : "=r"(r) : "r"(*(u32*)&h)); return r;
}
static __device__ __forceinline__ u32 packp(float a, float b) {
    return h2u(__floats2half2_rn(a, b));
}

__global__ void __launch_bounds__(THREADS, 1) phys_attn_pers(
    const float* __restrict__ x,
    const float* __restrict__ bq, const float* __restrict__ bk,
    const float* __restrict__ bv,
    const float* __restrict__ bias_emb, const int* __restrict__ hop,
    float* __restrict__ out)
{
    extern __shared__ __align__(16) char sm[];
    char* wks = sm + WKS_OFF;
    char* wvs = sm + WVS_OFF;
    char* wqb = sm + WQB_OFF;
    char* xs  = sm + XS_OFF;
    char* kps = sm + KPS_OFF;
    char* vps = sm + VPS_OFF;
    float* bias_s = (float*)(sm + BT_OFF);
    float* bqs    = (float*)(sm + BQ_OFF);
    float* bks    = (float*)(sm + BK_OFF);
    float* bvs    = (float*)(sm + BV_OFF);

    const int tid = threadIdx.x;
    const int wid = tid >> 5, lid = tid & 31;
    const int gr = lid >> 2, q4 = lid & 3;
    const int m0 = (wid >> 1) * 16;      // strip rows
    const int co = (wid & 1) * 64;       // col half

    const int arow = (lid & 7) + ((lid >> 3) & 1) * 8;
    const int acol = ((lid >> 4) & 1) * 8;
    const int brow = (lid & 7) + ((lid >> 4) & 1) * 8;
    const int bcol = ((lid >> 3) & 1) * 8;
    const int vrow = lid & 15;                 // trans-B k rows
    const int vcs  = ((lid >> 4) & 1) * 8;

    // staging mapping: one row per thread, 32 cols (conflict-free uint4 STS)
    const int sgm = tid & 127;            // row
    const int sgs = tid >> 7;             // col quarter (0..3)

    // ---- prologue ----
#pragma unroll
    for (int k = 0; k < 4; ++k) {
        int h0 = tid * 32 + k * 8;
        int off = swz(h0 >> 7, h0 & 127);
        *(uint4*)(wks + off) = *(const uint4*)(&g_wh[1][h0]);
        *(uint4*)(wvs + off) = *(const uint4*)(&g_wh[2][h0]);
    }
    if (tid < OO) {
        bqs[tid] = __ldg(bq + tid);
        bks[tid] = __ldg(bk + tid);
        bvs[tid] = __ldg(bv + tid);
    }
    for (int i = tid; i < VV * VV; i += THREADS)
        bias_s[i] = __ldg(bias_emb + __ldg(hop + i));

    int it = blockIdx.x;
    if (it < NITEMS) {
        int n = it / TILES, tile = it - n * TILES;
        int nval = (tile < 51) ? 125 : 25;
        const float* xb = x + (size_t)n * (CC * TT * VV) + (size_t)(tile * 5) * VV;
        bool mv = sgm < nval;
#pragma unroll
        for (int b2 = 0; b2 < 2; ++b2) {
            u32 h[8];
#pragma unroll
            for (int p = 0; p < 8; ++p) {
                int c = 32 * sgs + 16 * b2 + 2 * p;
                float v0 = mv ? __ldg(xb + (size_t)c * (TT * VV) + sgm) : 0.f;
                float v1 = mv ? __ldg(xb + (size_t)(c + 1) * (TT * VV) + sgm) : 0.f;
                h[p] = packp(v0, v1);
            }
            *(uint4*)(xs + swz(sgm, 32 * sgs + 16 * b2)) =
                make_uint4(h[0], h[1], h[2], h[3]);
            *(uint4*)(xs + swz(sgm, 32 * sgs + 16 * b2 + 8)) =
                make_uint4(h[4], h[5], h[6], h[7]);
        }
    }
    __syncthreads();

    for (; it < NITEMS; it += gridDim.x) {
        const int n = it / TILES, tile = it - n * TILES;
        const int t0 = tile * 5;
        const int nvalid = (tile < 51) ? 125 : 25;
        const int nit = it + gridDim.x;
        const bool hn = nit < NITEMS;
        int nnval = 0;
        const float* nxb = x;
        if (hn) {
            int nn = nit / TILES, ntile = nit - nn * TILES;
            nnval = (ntile < 51) ? 125 : 25;
            nxb = x + (size_t)nn * (CC * TT * VV) + (size_t)(ntile * 5) * VV;
        }
        const bool smv = hn && (sgm < nnval);

        // top: cache x A-frags; refill Wq image from L2
        u32 af[8][4];
#pragma unroll
        for (int kt = 0; kt < 8; ++kt)
            ldmx4(af[kt], xs + swz(m0 + arow, kt * 16 + acol));
#pragma unroll
        for (int k = 0; k < 4; ++k) {
            int h0 = tid * 32 + k * 8;
            *(uint4*)(wqb + swz(h0 >> 7, h0 & 127)) = *(const uint4*)(&g_wh[0][h0]);
        }
        __syncthreads();                      // BAR1

        float d[8][4];
        u32 b[4];
        u32 xp[8];

        // prefetch batch0 (cols 32s..32s+15) — overlaps K projection
        if (hn) {
#pragma unroll
            for (int p = 0; p < 8; ++p) {
                int c = 32 * sgs + 2 * p;
                float v0 = smv ? __ldg(nxb + (size_t)c * (TT * VV) + sgm) : 0.f;
                float v1 = smv ? __ldg(nxb + (size_t)(c + 1) * (TT * VV) + sgm) : 0.f;
                xp[p] = packp(v0, v1);
            }
        }

        // ---------- K projection -> K' ----------
#pragma unroll
        for (int j = 0; j < 8; ++j) { d[j][0]=d[j][1]=d[j][2]=d[j][3]=0.f; }
#pragma unroll
        for (int kt = 0; kt < 8; ++kt) {
#pragma unroll
            for (int jp = 0; jp < 4; ++jp) {
                ldmx4(b, wks + swz(co + jp * 16 + brow, kt * 16 + bcol));
                mma16816(d[2*jp],   af[kt][0],af[kt][1],af[kt][2],af[kt][3], b[0],b[1]);
                mma16816(d[2*jp+1], af[kt][0],af[kt][1],af[kt][2],af[kt][3], b[2],b[3]);
            }
        }
#pragma unroll
        for (int j = 0; j < 8; ++j) {
            int col = co + j * 8 + q4 * 2;
            float b0 = bks[col], b1 = bks[col + 1];
            *(__half2*)(kps + swz(m0 + gr, col)) =
                __floats2half2_rn(d[j][0] + b0, d[j][1] + b1);
            *(__half2*)(kps + swz(m0 + gr + 8, col)) =
                __floats2half2_rn(d[j][2] + b0, d[j][3] + b1);
        }
        // batch0 STS + batch1 LDG
        if (hn) {
            *(uint4*)(xs + swz(sgm, 32 * sgs)) =
                make_uint4(xp[0], xp[1], xp[2], xp[3]);
            *(uint4*)(xs + swz(sgm, 32 * sgs + 8)) =
                make_uint4(xp[4], xp[5], xp[6], xp[7]);
#pragma unroll
            for (int p = 0; p < 8; ++p) {
                int c = 32 * sgs + 16 + 2 * p;
                float v0 = smv ? __ldg(nxb + (size_t)c * (TT * VV) + sgm) : 0.f;
                float v1 = smv ? __ldg(nxb + (size_t)(c + 1) * (TT * VV) + sgm) : 0.f;
                xp[p] = packp(v0, v1);
            }
        }

        // ---------- V projection -> V' [m][o] ----------
#pragma unroll
        for (int j = 0; j < 8; ++j) { d[j][0]=d[j][1]=d[j][2]=d[j][3]=0.f; }
#pragma unroll
        for (int kt = 0; kt < 8; ++kt) {
#pragma unroll
            for (int jp = 0; jp < 4; ++jp) {
                ldmx4(b, wvs + swz(co + jp * 16 + brow, kt * 16 + bcol));
                mma16816(d[2*jp],   af[kt][0],af[kt][1],af[kt][2],af[kt][3], b[0],b[1]);
                mma16816(d[2*jp+1], af[kt][0],af[kt][1],af[kt][2],af[kt][3], b[2],b[3]);
            }
        }
#pragma unroll
        for (int j = 0; j < 8; ++j) {
            int col = co + j * 8 + q4 * 2;
            float b0 = bvs[col], b1 = bvs[col + 1];
            *(__half2*)(vps + swz(m0 + gr, col)) =
                __floats2half2_rn(d[j][0] + b0, d[j][1] + b1);
            *(__half2*)(vps + swz(m0 + gr + 8, col)) =
                __floats2half2_rn(d[j][2] + b0, d[j][3] + b1);
        }
        // batch1 STS
        if (hn) {
            *(uint4*)(xs + swz(sgm, 32 * sgs + 16)) =
                make_uint4(xp[0], xp[1], xp[2], xp[3]);
            *(uint4*)(xs + swz(sgm, 32 * sgs + 24)) =
                make_uint4(xp[4], xp[5], xp[6], xp[7]);
        }

        // ---------- Q projection (reads wqb) ----------
#pragma unroll
        for (int j = 0; j < 8; ++j) { d[j][0]=d[j][1]=d[j][2]=d[j][3]=0.f; }
#pragma unroll
        for (int kt = 0; kt < 8; ++kt) {
#pragma unroll
            for (int jp = 0; jp < 4; ++jp) {
                ldmx4(b, wqb + swz(co + jp * 16 + brow, kt * 16 + bcol));
                mma16816(d[2*jp],   af[kt][0],af[kt][1],af[kt][2],af[kt][3], b[0],b[1]);
                mma16816(d[2*jp+1], af[kt][0],af[kt][1],af[kt][2],af[kt][3], b[2],b[3]);
            }
        }
        __syncthreads();                      // BAR2: Wq reads done
#pragma unroll
        for (int j = 0; j < 8; ++j) {         // Q' (+bq) -> wqb
            int col = co + j * 8 + q4 * 2;
            float b0 = bqs[col], b1 = bqs[col + 1];
            *(__half2*)(wqb + swz(m0 + gr, col)) =
                __floats2half2_rn(d[j][0] + b0, d[j][1] + b1);
            *(__half2*)(wqb + swz(m0 + gr + 8, col)) =
                __floats2half2_rn(d[j][2] + b0, d[j][3] + b1);
        }
        __syncthreads();                      // BAR3: Q'/K'/V' visible

        // ======== S -> softmax -> AV (all 16 warps; pair splits AV cols) =====
        const bool wact = m0 < nvalid;
        const int mA = m0 + gr, mB = mA + 8;
        const bool actA = mA < nvalid, actB = mB < nvalid;
        const int loA = (mA / VV) * VV, loB = (mB / VV) * VV;
        const int vlA = mA - loA, vlB = mB - loB;
        int jlo = 0, jhi = 0, ktlo = 0, kthi = 0, dlt = 0;
        if (wact) {
            int rhi = min(m0 + 16, nvalid);
            int wlo = (m0 / VV) * VV;
            int whi = min(((rhi - 1) / VV) * VV + VV, nvalid);
            jlo = wlo >> 3; jhi = (whi + 7) >> 3;
            ktlo = wlo >> 4; kthi = (whi + 15) >> 4;
            dlt = 2 * ktlo - jlo;
        }
        float d2[7][4];
#pragma unroll
        for (int jt = 0; jt < 7; ++jt)
            d2[jt][0] = d2[jt][1] = d2[jt][2] = d2[jt][3] = 0.f;

        if (wact) {
#pragma unroll
            for (int kt = 0; kt < 8; ++kt) {
                u32 a[4];
                ldmx4(a, wqb + swz(m0 + arow, kt * 16 + acol));
#pragma unroll
                for (int jt = 0; jt < 7; ++jt) {
                    if (jlo + jt < jhi) {
                        int nrow = (jlo + jt) * 8 + gr;
                        int rb = nrow << 8;
                        u32 b0 = *(const u32*)(kps + rb +
                                  (((2 * kt) ^ (nrow & 7)) << 4) + (q4 << 2));
                        u32 b1 = *(const u32*)(kps + rb +
                                  (((2 * kt + 1) ^ (nrow & 7)) << 4) + (q4 << 2));
                        mma16816(d2[jt], a[0], a[1], a[2], a[3], b0, b1);
                    }
                }
            }
        }
        // register softmax
        float mxA = NEG_INF, mxB = NEG_INF;
#pragma unroll
        for (int jt = 0; jt < 7; ++jt) {
            int c0 = (jlo + jt) * 8 + q4 * 2;
            int rA = c0 - loA, rB = c0 - loB;
            float v;
            v = (actA && rA >= 0 && rA < VV)
                ? fmaf(d2[jt][0], SCALE, bias_s[vlA * VV + rA]) : NEG_INF;
            d2[jt][0] = v; mxA = fmaxf(mxA, v);
            v = (actA && rA + 1 >= 0 && rA + 1 < VV)
                ? fmaf(d2[jt][1], SCALE, bias_s[vlA * VV + rA + 1]) : NEG_INF;
            d2[jt][1] = v; mxA = fmaxf(mxA, v);
            v = (actB && rB >= 0 && rB < VV)
                ? fmaf(d2[jt][2], SCALE, bias_s[vlB * VV + rB]) : NEG_INF;
            d2[jt][2] = v; mxB = fmaxf(mxB, v);
            v = (actB && rB + 1 >= 0 && rB + 1 < VV)
                ? fmaf(d2[jt][3], SCALE, bias_s[vlB * VV + rB + 1]) : NEG_INF;
            d2[jt][3] = v; mxB = fmaxf(mxB, v);
        }
        mxA = fmaxf(mxA, __shfl_xor_sync(0xffffffffu, mxA, 1));
        mxA = fmaxf(mxA, __shfl_xor_sync(0xffffffffu, mxA, 2));
        mxB = fmaxf(mxB, __shfl_xor_sync(0xffffffffu, mxB, 1));
        mxB = fmaxf(mxB, __shfl_xor_sync(0xffffffffu, mxB, 2));
        float smA = 0.f, smB = 0.f;
#pragma unroll
        for (int jt = 0; jt < 7; ++jt) {
            float e0 = (d2[jt][0] > NEG_INF * 0.5f) ? __expf(d2[jt][0] - mxA) : 0.f;
            float e1 = (d2[jt][1] > NEG_INF * 0.5f) ? __expf(d2[jt][1] - mxA) : 0.f;
            float e2 = (d2[jt][2] > NEG_INF * 0.5f) ? __expf(d2[jt][2] - mxB) : 0.f;
            float e3 = (d2[jt][3] > NEG_INF * 0.5f) ? __expf(d2[jt][3] - mxB) : 0.f;
            d2[jt][0] = e0; d2[jt][1] = e1; d2[jt][2] = e2; d2[jt][3] = e3;
            smA += e0 + e1; smB += e2 + e3;
        }
        smA += __shfl_xor_sync(0xffffffffu, smA, 1);
        smA += __shfl_xor_sync(0xffffffffu, smA, 2);
        smB += __shfl_xor_sync(0xffffffffu, smB, 1);
        smB += __shfl_xor_sync(0xffffffffu, smB, 2);
        float ivA = (smA > 0.f) ? (1.f / smA) : 0.f;
        float ivB = (smB > 0.f) ? (1.f / smB) : 0.f;

        // pack P fragments (S acc layout == AV A-frag layout)
        u32 pa0[4], pa1[4], pa2[4], pa3[4];
#pragma unroll
        for (int kr = 0; kr < 4; ++kr) { pa0[kr]=pa1[kr]=pa2[kr]=pa3[kr]=0u; }
        if (dlt == 0) {
#pragma unroll
            for (int kr = 0; kr < 4; ++kr) {
                if (ktlo + kr < kthi) {
                    pa0[kr] = packp(d2[2*kr][0]*ivA, d2[2*kr][1]*ivA);
                    pa1[kr] = packp(d2[2*kr][2]*ivB, d2[2*kr][3]*ivB);
                    if (2*kr + 1 < 7) {
                        pa2[kr] = packp(d2[2*kr+1][0]*ivA, d2[2*kr+1][1]*ivA);
                        pa3[kr] = packp(d2[2*kr+1][2]*ivB, d2[2*kr+1][3]*ivB);
                    }
                }
            }
        } else {
#pragma unroll
            for (int kr = 0; kr < 4; ++kr) {
                if (ktlo + kr < kthi) {
                    if (2*kr - 1 >= 0) {
                        pa0[kr] = packp(d2[2*kr-1][0]*ivA, d2[2*kr-1][1]*ivA);
                        pa1[kr] = packp(d2[2*kr-1][2]*ivB, d2[2*kr-1][3]*ivB);
                    }
                    pa2[kr] = packp(d2[2*kr][0]*ivA, d2[2*kr][1]*ivA);
                    pa3[kr] = packp(d2[2*kr][2]*ivB, d2[2*kr][3]*ivB);
                }
            }
        }

        // AV = P V' : this warp's col half (64 cols), trans-B fragments
        float acc[8][4];
#pragma unroll
        for (int np = 0; np < 8; ++np)
            acc[np][0] = acc[np][1] = acc[np][2] = acc[np][3] = 0.f;
        if (wact) {
#pragma unroll
            for (int kr = 0; kr < 4; ++kr) {
                if (ktlo + kr < kthi) {
                    int ktv = ktlo + kr;
#pragma unroll
                    for (int jpp = 0; jpp < 4; ++jpp) {
                        int n0 = co + jpp * 16;
                        ldmx4t(b, vps + swz(ktv * 16 + vrow, n0 + vcs));
                        mma16816(acc[2*jpp],   pa0[kr],pa1[kr],pa2[kr],pa3[kr], b[0],b[1]);
                        mma16816(acc[2*jpp+1], pa0[kr],pa1[kr],pa2[kr],pa3[kr], b[2],b[3]);
                    }
                }
            }
        }
        __syncthreads();                      // BAR_END: all smem reads done

        // ---------- direct register -> gmem store (32B-sector aligned runs) ----
        float* ob = out + (size_t)n * (OO * TT * VV) + (size_t)t0 * VV;
        if (wact) {
#pragma unroll
            for (int np = 0; np < 8; ++np) {
                int col = co + np * 8 + q4 * 2;
                float* p0 = ob + (size_t)col * (TT * VV);
                if (actA) {
                    p0[mA] = acc[np][0];
                    p0[TT * VV + mA] = acc[np][1];
                }
                if (actB) {
                    p0[mB] = acc[np][2];
                    p0[TT * VV + mB] = acc[np][3];
                }
            }
        }
        // next iter BAR1 orders smem rewrites
    }
}

extern "C" void kernel_launch(void* const* d_in, const int* in_sizes, int n_in,
                              void* d_out, int out_size)
{
    const float* x   = (const float*)d_in[0];
    const float* wq  = (const float*)d_in[1];
    const float* bq  = (const float*)d_in[2];
    const float* wk  = (const float*)d_in[3];
    const float* bk  = (const float*)d_in[4];
    const float* wv  = (const float*)d_in[5];
    const float* bv  = (const float*)d_in[6];
    const float* be  = (const float*)d_in[7];
    const int*   hop = (const int*)d_in[8];
    float* out = (float*)d_out;

    int sms = 148;
    cudaDeviceGetAttribute(&sms, cudaDevAttrMultiProcessorCount, 0);

    cudaFuncSetAttribute(phys_attn_pers,
                         cudaFuncAttributeMaxDynamicSharedMemorySize, SMEM_BYTES);

    prep_w<<<(OO * CC + 255) / 256, 256>>>(wq, wk, wv);
    phys_attn_pers<<<sms, THREADS, SMEM_BYTES>>>(
        x, bq, bk, bv, be, hop, out);
}

// round 12
// speedup vs baseline: 1.8641x; 1.0798x over previous
#include <cuda_runtime.h>
#include <cuda_fp16.h>
#include <cstdint>

typedef unsigned int u32;

#define NN 64
#define CC 128
#define TT 256
#define VV 25
#define OO 128
#define TILES 52
#define NITEMS (NN * TILES)
#define THREADS 512
#define SCALE 0.08838834764831845f
#define NEG_INF (-1e30f)

// swizzled fp16 tiles: [128 rows][128 halves], row stride 256B, 16B-chunk XOR
#define WKS_OFF 0              // Wk (pristine)
#define WVS_OFF 32768          // Wv (pristine)
#define WQS_OFF 65536          // Wq (pristine -- never overwritten)
#define XS_OFF  98304          // x tile (streamed)
#define KPS_OFF 131072         // K'
#define VPS_OFF 163840         // V'
#define QPS_OFF 196608         // Q' (dedicated)
#define BT_OFF  229376         // bias table [25][25] f32
#define SMEM_BYTES 231936

__device__ __half g_wh[3][OO * CC];

__global__ void __launch_bounds__(256) prep_w(
    const float* __restrict__ wq, const float* __restrict__ wk,
    const float* __restrict__ wv)
{
    int i = blockIdx.x * blockDim.x + threadIdx.x;
    if (i < OO * CC) {
        g_wh[0][i] = __float2half_rn(wq[i]);
        g_wh[1][i] = __float2half_rn(wk[i]);
        g_wh[2][i] = __float2half_rn(wv[i]);
    }
}

static __device__ __forceinline__ int swz(int row, int colh) {
    return (row << 8) + ((((colh >> 3) ^ (row & 7))) << 4) + ((colh & 7) << 1);
}
static __device__ __forceinline__ void mma16816(
    float* d, u32 a0, u32 a1, u32 a2, u32 a3, u32 b0, u32 b1)
{
    asm volatile(
        "mma.sync.aligned.m16n8k16.row.col.f32.f16.f16.f32 "
        "{%0,%1,%2,%3}, {%4,%5,%6,%7}, {%8,%9}, {%0,%1,%2,%3};"
        : "+f"(d[0]), "+f"(d[1]), "+f"(d[2]), "+f"(d[3])
        : "r"(a0), "r"(a1), "r"(a2), "r"(a3), "r"(b0), "r"(b1));
}
static __device__ __forceinline__ void ldmx4(u32* r, const void* p) {
    u32 a = (u32)__cvta_generic_to_shared(p);
    asm volatile("ldmatrix.sync.aligned.m8n8.x4.shared.b16 {%0,%1,%2,%3}, [%4];"
        : "=r"(r[0]), "=r"(r[1]), "=r"(r[2]), "=r"(r[3]) : "r"(a));
}
static __device__ __forceinline__ void ldmx4t(u32* r, const void* p) {
    u32 a = (u32)__cvta_generic_to_shared(p);
    asm volatile("ldmatrix.sync.aligned.m8n8.x4.trans.shared.b16 {%0,%1,%2,%3}, [%4];"
        : "=r"(r[0]), "=r"(r[1]), "=r"(r[2]), "=r"(r[3]) : "r"(a));
}
static __device__ __forceinline__ u32 h2u(__half2 h) {
    u32 r; asm("mov.b32 %0, %1;" : "=r"(r) : "r"(*(u32*)&h)); return r;
}
static __device__ __forceinline__ u32 packp(float a, float b) {
    return h2u(__floats2half2_rn(a, b));
}

__global__ void __launch_bounds__(THREADS, 1) phys_attn_pers(
    const float* __restrict__ x,
    const float* __restrict__ bq, const float* __restrict__ bk,
    const float* __restrict__ bv,
    const float* __restrict__ bias_emb, const int* __restrict__ hop,
    float* __restrict__ out)
{
    extern __shared__ __align__(16) char sm[];
    char* wks = sm + WKS_OFF;
    char* wvs = sm + WVS_OFF;
    char* wqs = sm + WQS_OFF;
    char* xs  = sm + XS_OFF;
    char* kps = sm + KPS_OFF;
    char* vps = sm + VPS_OFF;
    char* qps = sm + QPS_OFF;
    float* bias_s = (float*)(sm + BT_OFF);

    const int tid = threadIdx.x;
    const int wid = tid >> 5, lid = tid & 31;
    const int gr = lid >> 2, q4 = lid & 3;
    const int m0 = (wid >> 1) * 16;      // strip rows
    const int co = (wid & 1) * 64;       // col half

    const int arow = (lid & 7) + ((lid >> 3) & 1) * 8;
    const int acol = ((lid >> 4) & 1) * 8;
    const int brow = (lid & 7) + ((lid >> 4) & 1) * 8;
    const int bcol = ((lid >> 3) & 1) * 8;
    const int vrow = lid & 15;                 // trans-B k rows
    const int vcs  = ((lid >> 4) & 1) * 8;

    // staging mapping: one row per thread, 32 cols (conflict-free uint4 STS)
    const int sgm = tid & 127;            // row
    const int sgs = tid >> 7;             // col quarter

    // ---- prologue: weights once, bias table ----
#pragma unroll
    for (int k = 0; k < 4; ++k) {
        int h0 = tid * 32 + k * 8;
        int off = swz(h0 >> 7, h0 & 127);
        *(uint4*)(wks + off) = *(const uint4*)(&g_wh[1][h0]);
        *(uint4*)(wvs + off) = *(const uint4*)(&g_wh[2][h0]);
        *(uint4*)(wqs + off) = *(const uint4*)(&g_wh[0][h0]);
    }
    for (int i = tid; i < VV * VV; i += THREADS)
        bias_s[i] = __ldg(bias_emb + __ldg(hop + i));

    int it = blockIdx.x;
    if (it < NITEMS) {
        int n = it / TILES, tile = it - n * TILES;
        int nval = (tile < 51) ? 125 : 25;
        const float* xb = x + (size_t)n * (CC * TT * VV) + (size_t)(tile * 5) * VV;
        bool mv = sgm < nval;
#pragma unroll
        for (int b2 = 0; b2 < 2; ++b2) {
            u32 h[8];
#pragma unroll
            for (int p = 0; p < 8; ++p) {
                int c = 32 * sgs + 16 * b2 + 2 * p;
                float v0 = mv ? __ldg(xb + (size_t)c * (TT * VV) + sgm) : 0.f;
                float v1 = mv ? __ldg(xb + (size_t)(c + 1) * (TT * VV) + sgm) : 0.f;
                h[p] = packp(v0, v1);
            }
            *(uint4*)(xs + swz(sgm, 32 * sgs + 16 * b2)) =
                make_uint4(h[0], h[1], h[2], h[3]);
            *(uint4*)(xs + swz(sgm, 32 * sgs + 16 * b2 + 8)) =
                make_uint4(h[4], h[5], h[6], h[7]);
        }
    }
    __syncthreads();

    for (; it < NITEMS; it += gridDim.x) {
        const int n = it / TILES, tile = it - n * TILES;
        const int t0 = tile * 5;
        const int nvalid = (tile < 51) ? 125 : 25;
        const int nit = it + gridDim.x;
        const bool hn = nit < NITEMS;
        int nnval = 0;
        const float* nxb = x;
        if (hn) {
            int nn = nit / TILES, ntile = nit - nn * TILES;
            nnval = (ntile < 51) ? 125 : 25;
            nxb = x + (size_t)nn * (CC * TT * VV) + (size_t)(ntile * 5) * VV;
        }
        const bool smv = hn && (sgm < nnval);
        const bool wact = m0 < nvalid;

        // top: cache this item's x A-frags (before xs gets restaged)
        u32 af[8][4];
        if (wact) {
#pragma unroll
            for (int kt = 0; kt < 8; ++kt)
                ldmx4(af[kt], xs + swz(m0 + arow, kt * 16 + acol));
        }
        __syncthreads();                      // BAR1

        float d[8][4];
        u32 b[4];
        u32 xp[8];

        // prefetch batch0 LDG (overlaps K projection)
        if (hn) {
#pragma unroll
            for (int p = 0; p < 8; ++p) {
                int c = 32 * sgs + 2 * p;
                float v0 = smv ? __ldg(nxb + (size_t)c * (TT * VV) + sgm) : 0.f;
                float v1 = smv ? __ldg(nxb + (size_t)(c + 1) * (TT * VV) + sgm) : 0.f;
                xp[p] = packp(v0, v1);
            }
        }

        // ---------- K projection -> K' ----------
        if (wact) {
#pragma unroll
            for (int j = 0; j < 8; ++j) { d[j][0]=d[j][1]=d[j][2]=d[j][3]=0.f; }
#pragma unroll
            for (int kt = 0; kt < 8; ++kt) {
#pragma unroll
                for (int jp = 0; jp < 4; ++jp) {
                    ldmx4(b, wks + swz(co + jp * 16 + brow, kt * 16 + bcol));
                    mma16816(d[2*jp],   af[kt][0],af[kt][1],af[kt][2],af[kt][3], b[0],b[1]);
                    mma16816(d[2*jp+1], af[kt][0],af[kt][1],af[kt][2],af[kt][3], b[2],b[3]);
                }
            }
#pragma unroll
            for (int j = 0; j < 8; ++j) {
                int col = co + j * 8 + q4 * 2;
                float2 bb = __ldg((const float2*)(bk + col));
                *(__half2*)(kps + swz(m0 + gr, col)) =
                    __floats2half2_rn(d[j][0] + bb.x, d[j][1] + bb.y);
                *(__half2*)(kps + swz(m0 + gr + 8, col)) =
                    __floats2half2_rn(d[j][2] + bb.x, d[j][3] + bb.y);
            }
        }
        // batch0 STS + batch1 LDG
        if (hn) {
            *(uint4*)(xs + swz(sgm, 32 * sgs)) =
                make_uint4(xp[0], xp[1], xp[2], xp[3]);
            *(uint4*)(xs + swz(sgm, 32 * sgs + 8)) =
                make_uint4(xp[4], xp[5], xp[6], xp[7]);
#pragma unroll
            for (int p = 0; p < 8; ++p) {
                int c = 32 * sgs + 16 + 2 * p;
                float v0 = smv ? __ldg(nxb + (size_t)c * (TT * VV) + sgm) : 0.f;
                float v1 = smv ? __ldg(nxb + (size_t)(c + 1) * (TT * VV) + sgm) : 0.f;
                xp[p] = packp(v0, v1);
            }
        }

        // ---------- V projection -> V' ----------
        if (wact) {
#pragma unroll
            for (int j = 0; j < 8; ++j) { d[j][0]=d[j][1]=d[j][2]=d[j][3]=0.f; }
#pragma unroll
            for (int kt = 0; kt < 8; ++kt) {
#pragma unroll
                for (int jp = 0; jp < 4; ++jp) {
                    ldmx4(b, wvs + swz(co + jp * 16 + brow, kt * 16 + bcol));
                    mma16816(d[2*jp],   af[kt][0],af[kt][1],af[kt][2],af[kt][3], b[0],b[1]);
                    mma16816(d[2*jp+1], af[kt][0],af[kt][1],af[kt][2],af[kt][3], b[2],b[3]);
                }
            }
#pragma unroll
            for (int j = 0; j < 8; ++j) {
                int col = co + j * 8 + q4 * 2;
                float2 bb = __ldg((const float2*)(bv + col));
                *(__half2*)(vps + swz(m0 + gr, col)) =
                    __floats2half2_rn(d[j][0] + bb.x, d[j][1] + bb.y);
                *(__half2*)(vps + swz(m0 + gr + 8, col)) =
                    __floats2half2_rn(d[j][2] + bb.x, d[j][3] + bb.y);
            }
        }
        // batch1 STS
        if (hn) {
            *(uint4*)(xs + swz(sgm, 32 * sgs + 16)) =
                make_uint4(xp[0], xp[1], xp[2], xp[3]);
            *(uint4*)(xs + swz(sgm, 32 * sgs + 24)) =
                make_uint4(xp[4], xp[5], xp[6], xp[7]);
        }

        // ---------- Q projection -> Q' (qps; Wq pristine, no refill) ----------
        if (wact) {
#pragma unroll
            for (int j = 0; j < 8; ++j) { d[j][0]=d[j][1]=d[j][2]=d[j][3]=0.f; }
#pragma unroll
            for (int kt = 0; kt < 8; ++kt) {
#pragma unroll
                for (int jp = 0; jp < 4; ++jp) {
                    ldmx4(b, wqs + swz(co + jp * 16 + brow, kt * 16 + bcol));
                    mma16816(d[2*jp],   af[kt][0],af[kt][1],af[kt][2],af[kt][3], b[0],b[1]);
                    mma16816(d[2*jp+1], af[kt][0],af[kt][1],af[kt][2],af[kt][3], b[2],b[3]);
                }
            }
#pragma unroll
            for (int j = 0; j < 8; ++j) {
                int col = co + j * 8 + q4 * 2;
                float2 bb = __ldg((const float2*)(bq + col));
                *(__half2*)(qps + swz(m0 + gr, col)) =
                    __floats2half2_rn(d[j][0] + bb.x, d[j][1] + bb.y);
                *(__half2*)(qps + swz(m0 + gr + 8, col)) =
                    __floats2half2_rn(d[j][2] + bb.x, d[j][3] + bb.y);
            }
        }
        __syncthreads();                      // BAR3: Q'/K'/V' visible

        // ======== S -> softmax -> AV (pair splits AV col halves) ========
        const int mA = m0 + gr, mB = mA + 8;
        const bool actA = mA < nvalid, actB = mB < nvalid;
        const int loA = (mA / VV) * VV, loB = (mB / VV) * VV;
        const int vlA = mA - loA, vlB = mB - loB;
        int jlo = 0, jhi = 0, ktlo = 0, kthi = 0, dlt = 0;
        if (wact) {
            int rhi = min(m0 + 16, nvalid);
            int wlo = (m0 / VV) * VV;
            int whi = min(((rhi - 1) / VV) * VV + VV, nvalid);
            jlo = wlo >> 3; jhi = (whi + 7) >> 3;
            ktlo = wlo >> 4; kthi = (whi + 15) >> 4;
            dlt = 2 * ktlo - jlo;
        }
        float d2[7][4];
#pragma unroll
        for (int jt = 0; jt < 7; ++jt)
            d2[jt][0] = d2[jt][1] = d2[jt][2] = d2[jt][3] = 0.f;

        if (wact) {
#pragma unroll
            for (int kt = 0; kt < 8; ++kt) {
                u32 a[4];
                ldmx4(a, qps + swz(m0 + arow, kt * 16 + acol));
#pragma unroll
                for (int jt = 0; jt < 7; ++jt) {
                    if (jlo + jt < jhi) {
                        int nrow = (jlo + jt) * 8 + gr;
                        int rb = nrow << 8;
                        u32 b0 = *(const u32*)(kps + rb +
                                  (((2 * kt) ^ (nrow & 7)) << 4) + (q4 << 2));
                        u32 b1 = *(const u32*)(kps + rb +
                                  (((2 * kt + 1) ^ (nrow & 7)) << 4) + (q4 << 2));
                        mma16816(d2[jt], a[0], a[1], a[2], a[3], b0, b1);
                    }
                }
            }
        }
        // register softmax
        float mxA = NEG_INF, mxB = NEG_INF;
#pragma unroll
        for (int jt = 0; jt < 7; ++jt) {
            int c0 = (jlo + jt) * 8 + q4 * 2;
            int rA = c0 - loA, rB = c0 - loB;
            float v;
            v = (actA && rA >= 0 && rA < VV)
                ? fmaf(d2[jt][0], SCALE, bias_s[vlA * VV + rA]) : NEG_INF;
            d2[jt][0] = v; mxA = fmaxf(mxA, v);
            v = (actA && rA + 1 >= 0 && rA + 1 < VV)
                ? fmaf(d2[jt][1], SCALE, bias_s[vlA * VV + rA + 1]) : NEG_INF;
            d2[jt][1] = v; mxA = fmaxf(mxA, v);
            v = (actB && rB >= 0 && rB < VV)
                ? fmaf(d2[jt][2], SCALE, bias_s[vlB * VV + rB]) : NEG_INF;
            d2[jt][2] = v; mxB = fmaxf(mxB, v);
            v = (actB && rB + 1 >= 0 && rB + 1 < VV)
                ? fmaf(d2[jt][3], SCALE, bias_s[vlB * VV + rB + 1]) : NEG_INF;
            d2[jt][3] = v; mxB = fmaxf(mxB, v);
        }
        mxA = fmaxf(mxA, __shfl_xor_sync(0xffffffffu, mxA, 1));
        mxA = fmaxf(mxA, __shfl_xor_sync(0xffffffffu, mxA, 2));
        mxB = fmaxf(mxB, __shfl_xor_sync(0xffffffffu, mxB, 1));
        mxB = fmaxf(mxB, __shfl_xor_sync(0xffffffffu, mxB, 2));
        float smA = 0.f, smB = 0.f;
#pragma unroll
        for (int jt = 0; jt < 7; ++jt) {
            float e0 = (d2[jt][0] > NEG_INF * 0.5f) ? __expf(d2[jt][0] - mxA) : 0.f;
            float e1 = (d2[jt][1] > NEG_INF * 0.5f) ? __expf(d2[jt][1] - mxA) : 0.f;
            float e2 = (d2[jt][2] > NEG_INF * 0.5f) ? __expf(d2[jt][2] - mxB) : 0.f;
            float e3 = (d2[jt][3] > NEG_INF * 0.5f) ? __expf(d2[jt][3] - mxB) : 0.f;
            d2[jt][0] = e0; d2[jt][1] = e1; d2[jt][2] = e2; d2[jt][3] = e3;
            smA += e0 + e1; smB += e2 + e3;
        }
        smA += __shfl_xor_sync(0xffffffffu, smA, 1);
        smA += __shfl_xor_sync(0xffffffffu, smA, 2);
        smB += __shfl_xor_sync(0xffffffffu, smB, 1);
        smB += __shfl_xor_sync(0xffffffffu, smB, 2);
        float ivA = (smA > 0.f) ? (1.f / smA) : 0.f;
        float ivB = (smB > 0.f) ? (1.f / smB) : 0.f;

        // pack P fragments (S acc layout == AV A-frag layout)
        u32 pa0[4], pa1[4], pa2[4], pa3[4];
#pragma unroll
        for (int kr = 0; kr < 4; ++kr) { pa0[kr]=pa1[kr]=pa2[kr]=pa3[kr]=0u; }
        if (dlt == 0) {
#pragma unroll
            for (int kr = 0; kr < 4; ++kr) {
                if (ktlo + kr < kthi) {
                    pa0[kr] = packp(d2[2*kr][0]*ivA, d2[2*kr][1]*ivA);
                    pa1[kr] = packp(d2[2*kr][2]*ivB, d2[2*kr][3]*ivB);
                    if (2*kr + 1 < 7) {
                        pa2[kr] = packp(d2[2*kr+1][0]*ivA, d2[2*kr+1][1]*ivA);
                        pa3[kr] = packp(d2[2*kr+1][2]*ivB, d2[2*kr+1][3]*ivB);
                    }
                }
            }
        } else {
#pragma unroll
            for (int kr = 0; kr < 4; ++kr) {
                if (ktlo + kr < kthi) {
                    if (2*kr - 1 >= 0) {
                        pa0[kr] = packp(d2[2*kr-1][0]*ivA, d2[2*kr-1][1]*ivA);
                        pa1[kr] = packp(d2[2*kr-1][2]*ivB, d2[2*kr-1][3]*ivB);
                    }
                    pa2[kr] = packp(d2[2*kr][0]*ivA, d2[2*kr][1]*ivA);
                    pa3[kr] = packp(d2[2*kr][2]*ivB, d2[2*kr][3]*ivB);
                }
            }
        }

        // AV = P V' : this warp's col half (64 cols), trans-B fragments
        float acc[8][4];
#pragma unroll
        for (int np = 0; np < 8; ++np)
            acc[np][0] = acc[np][1] = acc[np][2] = acc[np][3] = 0.f;
        if (wact) {
#pragma unroll
            for (int kr = 0; kr < 4; ++kr) {
                if (ktlo + kr < kthi) {
                    int ktv = ktlo + kr;
#pragma unroll
                    for (int jpp = 0; jpp < 4; ++jpp) {
                        int n0 = co + jpp * 16;
                        ldmx4t(b, vps + swz(ktv * 16 + vrow, n0 + vcs));
                        mma16816(acc[2*jpp],   pa0[kr],pa1[kr],pa2[kr],pa3[kr], b[0],b[1]);
                        mma16816(acc[2*jpp+1], pa0[kr],pa1[kr],pa2[kr],pa3[kr], b[2],b[3]);
                    }
                }
            }
        }

        // ---------- direct register -> gmem store ----------
        float* ob = out + (size_t)n * (OO * TT * VV) + (size_t)t0 * VV;
        if (wact) {
#pragma unroll
            for (int np = 0; np < 8; ++np) {
                int col = co + np * 8 + q4 * 2;
                float* p0 = ob + (size_t)col * (TT * VV);
                if (actA) {
                    p0[mA] = acc[np][0];
                    p0[TT * VV + mA] = acc[np][1];
                }
                if (actB) {
                    p0[mB] = acc[np][2];
                    p0[TT * VV + mB] = acc[np][3];
                }
            }
        }
        // next iter's BAR1 orders all smem reads above vs next writes
    }
}

extern "C" void kernel_launch(void* const* d_in, const int* in_sizes, int n_in,
                              void* d_out, int out_size)
{
    const float* x   = (const float*)d_in[0];
    const float* wq  = (const float*)d_in[1];
    const float* bq  = (const float*)d_in[2];
    const float* wk  = (const float*)d_in[3];
    const float* bk  = (const float*)d_in[4];
    const float* wv  = (const float*)d_in[5];
    const float* bv  = (const float*)d_in[6];
    const float* be  = (const float*)d_in[7];
    const int*   hop = (const int*)d_in[8];
    float* out = (float*)d_out;

    int sms = 148;
    cudaDeviceGetAttribute(&sms, cudaDevAttrMultiProcessorCount, 0);

    cudaFuncSetAttribute(phys_attn_pers,
                         cudaFuncAttributeMaxDynamicSharedMemorySize, SMEM_BYTES);

    prep_w<<<(OO * CC + 255) / 256, 256>>>(wq, wk, wv);
    phys_attn_pers<<<sms, THREADS, SMEM_BYTES>>>(
        x, bq, bk, bv, be, hop, out);
}